// round 10
// baseline (speedup 1.0000x reference)
#include <cuda_runtime.h>
#include <cuda_bf16.h>
#include <math.h>
#include <cstdint>

#define B_  4
#define S_  2048
#define D_  768
#define H_  12
#define DH_ 64
#define M_  (B_*S_)          // 8192
#define NROWS_ (B_*H_*S_)    // 98304
#define QKVN_ (NROWS_*DH_)   // 6291456
#define DD_  (D_*D_)         // 589824
#define LOG2E_ 1.4426950408889634f

// Scratch (allocation-free: static __device__ globals)
__device__ __nv_bfloat16 g_xh[M_*D_],  g_xl[M_*D_];
__device__ __nv_bfloat16 g_wh[4*DD_],  g_wl[4*DD_];
__device__ __nv_bfloat16 g_qh[QKVN_],  g_ql[QKVN_];
__device__ __nv_bfloat16 g_kh[QKVN_],  g_kl[QKVN_];
__device__ __nv_bfloat16 g_vh[QKVN_],  g_vl[QKVN_];
__device__ __nv_bfloat16 g_ch[M_*D_],  g_cl[M_*D_];

// ===========================================================================
// Helpers
// ===========================================================================
__device__ __forceinline__ uint32_t smem_u32(const void* p) {
    uint32_t r;
    asm("{ .reg .u64 t; cvta.to.shared.u64 t, %1; cvt.u32.u64 %0, t; }"
        : "=r"(r) : "l"(p));
    return r;
}
__device__ __forceinline__ void ldsm_x4(uint32_t* r, uint32_t addr) {
    asm volatile("ldmatrix.sync.aligned.m8n8.x4.shared.b16 {%0,%1,%2,%3}, [%4];"
                 : "=r"(r[0]), "=r"(r[1]), "=r"(r[2]), "=r"(r[3]) : "r"(addr));
}
__device__ __forceinline__ void ldsm_x4_t(uint32_t* r, uint32_t addr) {
    asm volatile("ldmatrix.sync.aligned.m8n8.x4.trans.shared.b16 {%0,%1,%2,%3}, [%4];"
                 : "=r"(r[0]), "=r"(r[1]), "=r"(r[2]), "=r"(r[3]) : "r"(addr));
}
__device__ __forceinline__ void mma16816(float* d, const uint32_t* a,
                                         uint32_t b0, uint32_t b1) {
    asm volatile(
        "mma.sync.aligned.m16n8k16.row.col.f32.bf16.bf16.f32 "
        "{%0,%1,%2,%3}, {%4,%5,%6,%7}, {%8,%9}, {%0,%1,%2,%3};"
        : "+f"(d[0]), "+f"(d[1]), "+f"(d[2]), "+f"(d[3])
        : "r"(a[0]), "r"(a[1]), "r"(a[2]), "r"(a[3]), "r"(b0), "r"(b1));
}
// round-to-nearest hi/lo split (off the hot path)
__device__ __forceinline__ void split2(float x0, float x1, uint32_t& hi, uint32_t& lo) {
    __nv_bfloat16 h0 = __float2bfloat16_rn(x0);
    __nv_bfloat16 h1 = __float2bfloat16_rn(x1);
    __nv_bfloat16 l0 = __float2bfloat16_rn(x0 - __bfloat162float(h0));
    __nv_bfloat16 l1 = __float2bfloat16_rn(x1 - __bfloat162float(h1));
    hi = (uint32_t)__bfloat16_as_ushort(h0) | ((uint32_t)__bfloat16_as_ushort(h1) << 16);
    lo = (uint32_t)__bfloat16_as_ushort(l0) | ((uint32_t)__bfloat16_as_ushort(l1) << 16);
}
// cheap truncation split for softmax P (hot path): hi = trunc, lo = residue
__device__ __forceinline__ void psplit(float x0, float x1, uint32_t& hi, uint32_t& lo) {
    const uint32_t u0 = __float_as_uint(x0), u1 = __float_as_uint(x1);
    hi = __byte_perm(u0, u1, 0x7632);
    const float l0 = x0 - __uint_as_float(u0 & 0xFFFF0000u);
    const float l1 = x1 - __uint_as_float(u1 & 0xFFFF0000u);
    asm("cvt.rn.bf16x2.f32 %0, %1, %2;" : "=r"(lo) : "f"(l1), "f"(l0));
}
__device__ __forceinline__ float ex2(float x) {
    float y;
    asm("ex2.approx.f32 %0, %1;" : "=f"(y) : "f"(x));
    return y;
}
__device__ __forceinline__ void cp16(uint32_t dst, const void* src) {
    asm volatile("cp.async.cg.shared.global [%0], [%1], 16;" :: "r"(dst), "l"(src));
}
#define CP_COMMIT() asm volatile("cp.async.commit_group;" ::: "memory")
#define CP_WAIT(n)  asm volatile("cp.async.wait_group %0;" :: "n"(n) : "memory")

// ===========================================================================
// split kernels: fp32 -> bf16 hi/lo
// ===========================================================================
__global__ void __launch_bounds__(256)
xsplit_kernel(const float* __restrict__ src)
{
    const int i = (blockIdx.x * 256 + threadIdx.x) * 4;
    float4 v = *reinterpret_cast<const float4*>(src + i);
    uint32_t h0, l0, h1, l1;
    split2(v.x, v.y, h0, l0);
    split2(v.z, v.w, h1, l1);
    *reinterpret_cast<uint2*>(g_xh + i) = make_uint2(h0, h1);
    *reinterpret_cast<uint2*>(g_xl + i) = make_uint2(l0, l1);
}
__global__ void __launch_bounds__(256)
wsplit_kernel(const float* __restrict__ Wq, const float* __restrict__ Wk,
              const float* __restrict__ Wv, const float* __restrict__ Wo)
{
    const int per = DD_ / 1024;                   // 576
    const int wsel = blockIdx.x / per;
    const int bx   = blockIdx.x % per;
    const float* src = (wsel == 0) ? Wq : (wsel == 1) ? Wk : (wsel == 2) ? Wv : Wo;
    const int i = (bx * 256 + threadIdx.x) * 4;
    float4 v = *reinterpret_cast<const float4*>(src + i);
    uint32_t h0, l0, h1, l1;
    split2(v.x, v.y, h0, l0);
    split2(v.z, v.w, h1, l1);
    const size_t o = (size_t)wsel * DD_ + i;
    *reinterpret_cast<uint2*>(g_wh + o) = make_uint2(h0, h1);
    *reinterpret_cast<uint2*>(g_wl + o) = make_uint2(l0, l1);
}

// ===========================================================================
// GEMM mainloop (bf16 pre-split inputs): acc = A @ W^T, 128x128 tile
// ===========================================================================
#define LDK_  40
#define GARR  10240
#define GEMM_SMEM (8 * GARR)        // 80KB

__device__ __forceinline__ void gemm_body(
    const __nv_bfloat16* __restrict__ Ah, const __nv_bfloat16* __restrict__ Al,
    const __nv_bfloat16* __restrict__ Wh, const __nv_bfloat16* __restrict__ Wl,
    int m0, int n0, char* smem, float acc[4][4][4])
{
    const int tid    = threadIdx.x;
    const int lane   = tid & 31;
    const int wid    = tid >> 5;
    const int warp_m = wid & 1;
    const int warp_n = wid >> 1;
    const uint32_t sb = smem_u32(smem);

#pragma unroll
    for (int i = 0; i < 4; i++)
#pragma unroll
        for (int j = 0; j < 4; j++)
#pragma unroll
            for (int e = 0; e < 4; e++) acc[i][j][e] = 0.f;

    const int grow = tid >> 1;
    const int c16  = (tid & 1) * 2;
    const __nv_bfloat16* s0 = Ah + (size_t)(m0 + grow) * D_;
    const __nv_bfloat16* s1 = Al + (size_t)(m0 + grow) * D_;
    const __nv_bfloat16* s2 = Wh + (size_t)(n0 + grow) * D_;
    const __nv_bfloat16* s3 = Wl + (size_t)(n0 + grow) * D_;

    auto issue = [&](int kc, int bsel) {
        const uint32_t dst = sb + bsel * 4 * GARR + grow * 80 + c16 * 16;
#pragma unroll
        for (int j = 0; j < 2; j++) {
            cp16(dst + j * 16,            s0 + kc + (c16 + j) * 8);
            cp16(dst + j * 16 + GARR,     s1 + kc + (c16 + j) * 8);
            cp16(dst + j * 16 + 2 * GARR, s2 + kc + (c16 + j) * 8);
            cp16(dst + j * 16 + 3 * GARR, s3 + kc + (c16 + j) * 8);
        }
    };

    const int r_a = lane & 15, c_a = (lane >> 4) * 8;
    const int r_b = (lane & 7) | ((lane >> 4) << 3);
    const int c_b = ((lane >> 3) & 1) * 8;
    const uint32_t offA = ((warp_m * 64 + r_a) * LDK_ + c_a) * 2;
    const uint32_t offB = ((warp_n * 32 + r_b) * LDK_ + c_b) * 2;

    issue(0, 0);
    CP_COMMIT();

    const int NK = D_ / 32;   // 24
    for (int it = 0; it < NK; it++) {
        if (it + 1 < NK) {
            issue((it + 1) * 32, (it + 1) & 1);
            CP_COMMIT();
            CP_WAIT(1);
        } else {
            CP_WAIT(0);
        }
        __syncthreads();

        const uint32_t bAh = sb + ((it & 1) * 4 + 0) * GARR;
        const uint32_t bAl = bAh + GARR;
        const uint32_t bWh = bAh + 2 * GARR;
        const uint32_t bWl = bAh + 3 * GARR;

#pragma unroll
        for (int ks = 0; ks < 2; ks++) {
            const uint32_t ko = ks * 32;
            uint32_t ah[4][4], al[4][4];
#pragma unroll
            for (int mt = 0; mt < 4; mt++) {
                ldsm_x4(ah[mt], bAh + offA + ko + mt * 16 * LDK_ * 2);
                ldsm_x4(al[mt], bAl + offA + ko + mt * 16 * LDK_ * 2);
            }
            uint32_t bh[8], bl[8];
#pragma unroll
            for (int g = 0; g < 2; g++) {
                ldsm_x4(&bh[g * 4], bWh + offB + ko + g * 16 * LDK_ * 2);
                ldsm_x4(&bl[g * 4], bWl + offB + ko + g * 16 * LDK_ * 2);
            }
#pragma unroll
            for (int mt = 0; mt < 4; mt++)
#pragma unroll
                for (int nt = 0; nt < 4; nt++) {
                    mma16816(acc[mt][nt], ah[mt], bh[nt * 2], bh[nt * 2 + 1]);
                    mma16816(acc[mt][nt], ah[mt], bl[nt * 2], bl[nt * 2 + 1]);
                    mma16816(acc[mt][nt], al[mt], bh[nt * 2], bh[nt * 2 + 1]);
                }
        }
        __syncthreads();
    }
}

// ===========================================================================
// fused QKV GEMM: proj + bias + (L2 norm + scale for q,k) + bf16 split store.
// ===========================================================================
__global__ void __launch_bounds__(256, 2)
qkv_gemm(const float* __restrict__ bq, const float* __restrict__ bk,
         const float* __restrict__ bv, const float* __restrict__ ls)
{
    extern __shared__ char smem[];
    const int wsel = blockIdx.x / 6;
    const int n0   = (blockIdx.x % 6) * 128;
    const int m0   = blockIdx.y * 128;

    float acc[4][4][4];
    gemm_body(g_xh, g_xl, g_wh + (size_t)wsel * DD_, g_wl + (size_t)wsel * DD_,
              m0, n0, smem, acc);

    const int tid  = threadIdx.x;
    const int lane = tid & 31;
    const int wid  = tid >> 5;
    const int warp_m = wid & 1, warp_n = wid >> 1;

    const float* bias = (wsel == 0) ? bq : (wsel == 1) ? bk : bv;
    __nv_bfloat16* dh = (wsel == 0) ? g_qh : (wsel == 1) ? g_kh : g_vh;
    __nv_bfloat16* dl = (wsel == 0) ? g_ql : (wsel == 1) ? g_kl : g_vl;

    float2 bv2[4];
#pragma unroll
    for (int nt = 0; nt < 4; nt++)
        bv2[nt] = *reinterpret_cast<const float2*>(
            &bias[n0 + warp_n * 32 + nt * 8 + 2 * (lane & 3)]);
#pragma unroll
    for (int mt = 0; mt < 4; mt++)
#pragma unroll
        for (int nt = 0; nt < 4; nt++) {
            acc[mt][nt][0] += bv2[nt].x; acc[mt][nt][1] += bv2[nt].y;
            acc[mt][nt][2] += bv2[nt].x; acc[mt][nt][3] += bv2[nt].y;
        }

    __syncthreads();
    float* sq = reinterpret_cast<float*>(smem);   // [128][4]

    if (wsel < 2) {
#pragma unroll
        for (int mt = 0; mt < 4; mt++)
#pragma unroll
            for (int half = 0; half < 2; half++) {
                const int r = warp_m * 64 + mt * 16 + (lane >> 2) + half * 8;
                float p = 0.f;
#pragma unroll
                for (int nt = 0; nt < 4; nt++) {
                    const float a = acc[mt][nt][half * 2], bvv = acc[mt][nt][half * 2 + 1];
                    p += a * a + bvv * bvv;
                }
                p += __shfl_xor_sync(0xffffffffu, p, 1);
                p += __shfl_xor_sync(0xffffffffu, p, 2);
                if ((lane & 3) == 0) sq[r * 4 + warp_n] = p;
            }
        __syncthreads();
    }

    float scl = 1.f;
    if (wsel == 0) {
        const int hh = 2 * (blockIdx.x % 6) + (warp_n >> 1);
        scl = __expf(fminf(ls[hh], 4.6051701859880914f)) * LOG2E_;
    }

#pragma unroll
    for (int mt = 0; mt < 4; mt++) {
#pragma unroll
        for (int half = 0; half < 2; half++) {
            const int r = warp_m * 64 + mt * 16 + (lane >> 2) + half * 8;
            float inv = 1.f;
            if (wsel < 2) {
                const float s2 = sq[r * 4 + (warp_n & 2)] + sq[r * 4 + (warp_n & 2) + 1];
                inv = scl / fmaxf(sqrtf(s2), 1e-12f);
            }
            const int m  = m0 + r;
            const int bb = m >> 11, ss = m & (S_ - 1);
#pragma unroll
            for (int nt = 0; nt < 4; nt++) {
                const int n  = n0 + warp_n * 32 + nt * 8 + 2 * (lane & 3);
                const int hh = n >> 6, dd = n & 63;
                const size_t idx = (((size_t)(bb * H_ + hh)) * S_ + ss) * DH_ + dd;
                uint32_t hi, lo;
                split2(acc[mt][nt][half * 2] * inv, acc[mt][nt][half * 2 + 1] * inv, hi, lo);
                *reinterpret_cast<uint32_t*>(&dh[idx]) = hi;
                *reinterpret_cast<uint32_t*>(&dl[idx]) = lo;
            }
        }
    }
}

// output GEMM: ctx(split) @ Wo^T + bo -> d_out
__global__ void __launch_bounds__(256, 2)
o_gemm(const float* __restrict__ bo, float* __restrict__ out)
{
    extern __shared__ char smem[];
    const int n0 = blockIdx.x * 128;
    const int m0 = blockIdx.y * 128;

    float acc[4][4][4];
    gemm_body(g_ch, g_cl, g_wh + 3 * (size_t)DD_, g_wl + 3 * (size_t)DD_,
              m0, n0, smem, acc);

    const int lane = threadIdx.x & 31;
    const int wid  = threadIdx.x >> 5;
    const int warp_m = wid & 1, warp_n = wid >> 1;
#pragma unroll
    for (int mt = 0; mt < 4; mt++) {
#pragma unroll
        for (int nt = 0; nt < 4; nt++) {
            const int n = n0 + warp_n * 32 + nt * 8 + 2 * (lane & 3);
            const float2 bv2 = *reinterpret_cast<const float2*>(&bo[n]);
#pragma unroll
            for (int half = 0; half < 2; half++) {
                const int m = m0 + warp_m * 64 + mt * 16 + (lane >> 2) + half * 8;
                float2 o;
                o.x = acc[mt][nt][half * 2 + 0] + bv2.x;
                o.y = acc[mt][nt][half * 2 + 1] + bv2.y;
                *reinterpret_cast<float2*>(out + (size_t)m * D_ + n) = o;
            }
        }
    }
}

// ===========================================================================
// HMMA flash attention: 4 warps/CTA, 32 q-rows per warp (K/V fragment loads
// amortize over 2x the rows -> smem traffic per SM halves, tensor work same).
// Fixed-max softmax, bf16x3 QK, trunc-split P PV (proven numerics).
// ===========================================================================
#define ABUF   9216
#define ATTN_SMEM (12 * ABUF)      // 3 buffers x {Kh,Kl,Vh,Vl}

__global__ void __launch_bounds__(128, 2)
attn_mma(const float* __restrict__ ls)
{
    extern __shared__ char sm[];
    const uint32_t sbase = smem_u32(sm);
    const int tid  = threadIdx.x;
    const int lane = tid & 31;
    const int wid  = tid >> 5;          // 0..3
    const int bh   = blockIdx.y;
    const int h    = bh % H_;
    const int b    = bh / H_;
    const int q0   = blockIdx.x * 128;
    const size_t base = (size_t)bh * S_ * DH_;
    const float Mfix = __expf(fminf(ls[h], 4.6051701859880914f)) * LOG2E_;

    // stage Q hi/lo (2 arrays x 128 rows x 128B) into smem, 16 uint4/thread
    {
        const __nv_bfloat16* gq0 = g_qh + base + (size_t)q0 * DH_;
        const __nv_bfloat16* gq1 = g_ql + base + (size_t)q0 * DH_;
#pragma unroll
        for (int i = 0; i < 16; i++) {
            const int idx = i * 128 + tid;          // 0..2047
            const int arr = idx >> 10;
            const int row = (idx >> 3) & 127;
            const int c   = idx & 7;
            const uint4 v = *reinterpret_cast<const uint4*>(
                (arr ? gq1 : gq0) + row * DH_ + c * 8);
            *reinterpret_cast<uint4*>(sm + arr * 18432 + row * 144 + c * 16) = v;
        }
    }
    __syncthreads();

    // A-fragments: warp covers rows wid*32 .. wid*32+31 (2 m16 tiles)
    uint32_t qfh[2][4][4], qfl[2][4][4];
#pragma unroll
    for (int mt = 0; mt < 2; mt++) {
        const uint32_t qa = sbase + (wid * 32 + mt * 16 + (lane & 15)) * 144
                          + (lane >> 4) * 16;
#pragma unroll
        for (int kt = 0; kt < 4; kt++) {
            ldsm_x4(qfh[mt][kt], qa + kt * 32);
            ldsm_x4(qfl[mt][kt], qa + 18432 + kt * 32);
        }
    }
    __syncthreads();

    float o[2][8][4];
#pragma unroll
    for (int mt = 0; mt < 2; mt++)
#pragma unroll
        for (int nt = 0; nt < 8; nt++)
#pragma unroll
            for (int e = 0; e < 4; e++) o[mt][nt][e] = 0.f;
    float lsum[2][2] = {{0.f, 0.f}, {0.f, 0.f}};

    const uint32_t lofs = (lane & 15) * 144 + (lane >> 4) * 16;

    const __nv_bfloat16* gkh = g_kh + base;
    const __nv_bfloat16* gkl = g_kl + base;
    const __nv_bfloat16* gvh = g_vh + base;
    const __nv_bfloat16* gvl = g_vl + base;

    // KV tile load: 4 arrays x 64 rows x 128B = 2048 x 16B chunks, 16/thread
    auto issue = [&](int it, int bsel) {
        const int koff = it * 64 * DH_;
#pragma unroll
        for (int i = 0; i < 16; i++) {
            const int idx = i * 128 + tid;          // 0..2047
            const int arr = idx >> 9;               // 0..3
            const int row = (idx >> 3) & 63;
            const int c   = idx & 7;
            const __nv_bfloat16* gp =
                (arr == 0 ? gkh : arr == 1 ? gkl : arr == 2 ? gvh : gvl)
                + koff + row * DH_ + c * 8;
            cp16(sbase + (bsel * 4 + arr) * ABUF + row * 144 + c * 16, gp);
        }
    };

    issue(0, 0); CP_COMMIT();
    issue(1, 1); CP_COMMIT();

    const int NIT = S_ / 64;   // 32
    for (int it = 0; it < NIT; it++) {
        if (it + 1 < NIT) { CP_WAIT(1); } else { CP_WAIT(0); }
        __syncthreads();
        if (it + 2 < NIT) { issue(it + 2, (it + 2) % 3); CP_COMMIT(); }

        const uint32_t Kh = sbase + ((it % 3) * 4) * ABUF;
        const uint32_t Kl = Kh + ABUF;
        const uint32_t Vh = Kh + 2 * ABUF;
        const uint32_t Vl = Kh + 3 * ABUF;

        // QK for one 16-key block g -> s[2 mt][2 n8][4] (logits - M)
        auto qk_block = [&](int g, float s[2][2][4]) {
#pragma unroll
            for (int mt = 0; mt < 2; mt++)
#pragma unroll
                for (int n = 0; n < 2; n++)
#pragma unroll
                    for (int e = 0; e < 4; e++) s[mt][n][e] = -Mfix;
#pragma unroll
            for (int kt = 0; kt < 4; kt++) {
                uint32_t kf[4], lf[4];
                ldsm_x4(kf, Kh + lofs + g * 16 * 144 + kt * 32);
                ldsm_x4(lf, Kl + lofs + g * 16 * 144 + kt * 32);
#pragma unroll
                for (int mt = 0; mt < 2; mt++) {
                    mma16816(s[mt][0], qfh[mt][kt], kf[0], kf[2]);
                    mma16816(s[mt][0], qfh[mt][kt], lf[0], lf[2]);
                    mma16816(s[mt][0], qfl[mt][kt], kf[0], kf[2]);
                    mma16816(s[mt][1], qfh[mt][kt], kf[1], kf[3]);
                    mma16816(s[mt][1], qfh[mt][kt], lf[1], lf[3]);
                    mma16816(s[mt][1], qfl[mt][kt], kf[1], kf[3]);
                }
            }
        };
        // exp2 + trunc-split pack + l accumulation
        auto exppack = [&](float s[2][2][4], uint32_t ph[2][4], uint32_t pl[2][4]) {
#pragma unroll
            for (int mt = 0; mt < 2; mt++) {
#pragma unroll
                for (int n = 0; n < 2; n++) {
                    s[mt][n][0] = ex2(s[mt][n][0]);
                    s[mt][n][1] = ex2(s[mt][n][1]);
                    s[mt][n][2] = ex2(s[mt][n][2]);
                    s[mt][n][3] = ex2(s[mt][n][3]);
                    lsum[mt][0] += s[mt][n][0] + s[mt][n][1];
                    lsum[mt][1] += s[mt][n][2] + s[mt][n][3];
                    psplit(s[mt][n][0], s[mt][n][1], ph[mt][2 * n],     pl[mt][2 * n]);
                    psplit(s[mt][n][2], s[mt][n][3], ph[mt][2 * n + 1], pl[mt][2 * n + 1]);
                }
            }
        };
        // PV of block g: o += P_g @ V_g (bf16x3: ph*Vh + ph*Vl + pl*Vh)
        auto pv_block = [&](int g, uint32_t ph[2][4], uint32_t pl[2][4]) {
#pragma unroll
            for (int og = 0; og < 4; og++) {
                uint32_t vf[4], wf[4];
                ldsm_x4_t(vf, Vh + lofs + g * 16 * 144 + og * 32);
                ldsm_x4_t(wf, Vl + lofs + g * 16 * 144 + og * 32);
#pragma unroll
                for (int mt = 0; mt < 2; mt++) {
                    mma16816(o[mt][2 * og],     ph[mt], vf[0], vf[1]);
                    mma16816(o[mt][2 * og],     ph[mt], wf[0], wf[1]);
                    mma16816(o[mt][2 * og],     pl[mt], vf[0], vf[1]);
                    mma16816(o[mt][2 * og + 1], ph[mt], vf[2], vf[3]);
                    mma16816(o[mt][2 * og + 1], ph[mt], wf[2], wf[3]);
                    mma16816(o[mt][2 * og + 1], pl[mt], vf[2], vf[3]);
                }
            }
        };

        float sA[2][2][4], sB[2][2][4];
        uint32_t phA[2][4], plA[2][4], phB[2][4], plB[2][4];

        qk_block(0, sA);
        exppack(sA, phA, plA);

        qk_block(1, sB);
        pv_block(0, phA, plA);
        exppack(sB, phB, plB);

        qk_block(2, sA);
        pv_block(1, phB, plB);
        exppack(sA, phA, plA);

        qk_block(3, sB);
        pv_block(2, phA, plA);
        exppack(sB, phB, plB);

        pv_block(3, phB, plB);
    }

    // epilogue: quad-reduce l, normalize, store ctx as bf16 hi/lo splits
#pragma unroll
    for (int mt = 0; mt < 2; mt++) {
        float l0 = lsum[mt][0], l1 = lsum[mt][1];
        l0 += __shfl_xor_sync(0xffffffffu, l0, 1);
        l0 += __shfl_xor_sync(0xffffffffu, l0, 2);
        l1 += __shfl_xor_sync(0xffffffffu, l1, 1);
        l1 += __shfl_xor_sync(0xffffffffu, l1, 2);
        const float inv0 = 1.f / l0;
        const float inv1 = 1.f / l1;
        const int row0 = q0 + wid * 32 + mt * 16 + (lane >> 2);
        const int col0 = h * DH_ + 2 * (lane & 3);
        const size_t p0 = ((size_t)b * S_ + row0) * D_ + col0;
        const size_t p1 = p0 + 8 * D_;
#pragma unroll
        for (int nt = 0; nt < 8; nt++) {
            uint32_t hi, lo;
            split2(o[mt][nt][0] * inv0, o[mt][nt][1] * inv0, hi, lo);
            *reinterpret_cast<uint32_t*>(g_ch + p0 + nt * 8) = hi;
            *reinterpret_cast<uint32_t*>(g_cl + p0 + nt * 8) = lo;
            split2(o[mt][nt][2] * inv1, o[mt][nt][3] * inv1, hi, lo);
            *reinterpret_cast<uint32_t*>(g_ch + p1 + nt * 8) = hi;
            *reinterpret_cast<uint32_t*>(g_cl + p1 + nt * 8) = lo;
        }
    }
}

// ---------------------------------------------------------------------------
// Launch
// ---------------------------------------------------------------------------
extern "C" void kernel_launch(void* const* d_in, const int* in_sizes, int n_in,
                              void* d_out, int out_size)
{
    const float* x  = (const float*)d_in[0];
    const float* Wq = (const float*)d_in[1];
    const float* bq = (const float*)d_in[2];
    const float* Wk = (const float*)d_in[3];
    const float* bk = (const float*)d_in[4];
    const float* Wv = (const float*)d_in[5];
    const float* bv = (const float*)d_in[6];
    const float* Wo = (const float*)d_in[7];
    const float* bo = (const float*)d_in[8];
    const float* ls = (const float*)d_in[9];
    float* out = (float*)d_out;

    xsplit_kernel<<<(M_ * D_) / 1024, 256>>>(x);
    wsplit_kernel<<<4 * (DD_ / 1024), 256>>>(Wq, Wk, Wv, Wo);

    cudaFuncSetAttribute(qkv_gemm, cudaFuncAttributeMaxDynamicSharedMemorySize, GEMM_SMEM);
    cudaFuncSetAttribute(o_gemm,   cudaFuncAttributeMaxDynamicSharedMemorySize, GEMM_SMEM);
    cudaFuncSetAttribute(attn_mma, cudaFuncAttributeMaxDynamicSharedMemorySize, ATTN_SMEM);

    qkv_gemm<<<dim3(18, M_ / 128), 256, GEMM_SMEM>>>(bq, bk, bv, ls);

    attn_mma<<<dim3(S_ / 128, B_ * H_), 128, ATTN_SMEM>>>(ls);

    o_gemm<<<dim3(D_ / 128, M_ / 128), 256, GEMM_SMEM>>>(bo, out);
}

// round 11
// speedup vs baseline: 1.0852x; 1.0852x over previous
#include <cuda_runtime.h>
#include <cuda_bf16.h>
#include <cuda_fp16.h>
#include <math.h>
#include <cstdint>

#define B_  4
#define S_  2048
#define D_  768
#define H_  12
#define DH_ 64
#define M_  (B_*S_)          // 8192
#define NROWS_ (B_*H_*S_)    // 98304
#define QKVN_ (NROWS_*DH_)   // 6291456
#define DD_  (D_*D_)         // 589824
#define LOG2E_ 1.4426950408889634f

// Scratch (allocation-free: static __device__ globals)
__device__ __nv_bfloat16 g_xh[M_*D_],  g_xl[M_*D_];
__device__ __nv_bfloat16 g_wh[4*DD_],  g_wl[4*DD_];
__device__ __nv_bfloat16 g_qh[QKVN_],  g_ql[QKVN_];
__device__ __nv_bfloat16 g_kh[QKVN_],  g_kl[QKVN_];
__device__ __half        g_vh[QKVN_],  g_vl[QKVN_];     // V is fp16 split
__device__ __nv_bfloat16 g_ch[M_*D_],  g_cl[M_*D_];

// ===========================================================================
// Helpers
// ===========================================================================
__device__ __forceinline__ uint32_t smem_u32(const void* p) {
    uint32_t r;
    asm("{ .reg .u64 t; cvta.to.shared.u64 t, %1; cvt.u32.u64 %0, t; }"
        : "=r"(r) : "l"(p));
    return r;
}
__device__ __forceinline__ void ldsm_x4(uint32_t* r, uint32_t addr) {
    asm volatile("ldmatrix.sync.aligned.m8n8.x4.shared.b16 {%0,%1,%2,%3}, [%4];"
                 : "=r"(r[0]), "=r"(r[1]), "=r"(r[2]), "=r"(r[3]) : "r"(addr));
}
__device__ __forceinline__ void ldsm_x4_t(uint32_t* r, uint32_t addr) {
    asm volatile("ldmatrix.sync.aligned.m8n8.x4.trans.shared.b16 {%0,%1,%2,%3}, [%4];"
                 : "=r"(r[0]), "=r"(r[1]), "=r"(r[2]), "=r"(r[3]) : "r"(addr));
}
// bf16 in, fp32 accum
__device__ __forceinline__ void mma16816(float* d, const uint32_t* a,
                                         uint32_t b0, uint32_t b1) {
    asm volatile(
        "mma.sync.aligned.m16n8k16.row.col.f32.bf16.bf16.f32 "
        "{%0,%1,%2,%3}, {%4,%5,%6,%7}, {%8,%9}, {%0,%1,%2,%3};"
        : "+f"(d[0]), "+f"(d[1]), "+f"(d[2]), "+f"(d[3])
        : "r"(a[0]), "r"(a[1]), "r"(a[2]), "r"(a[3]), "r"(b0), "r"(b1));
}
// fp16 in, fp32 accum
__device__ __forceinline__ void mma16816h(float* d, const uint32_t* a,
                                          uint32_t b0, uint32_t b1) {
    asm volatile(
        "mma.sync.aligned.m16n8k16.row.col.f32.f16.f16.f32 "
        "{%0,%1,%2,%3}, {%4,%5,%6,%7}, {%8,%9}, {%0,%1,%2,%3};"
        : "+f"(d[0]), "+f"(d[1]), "+f"(d[2]), "+f"(d[3])
        : "r"(a[0]), "r"(a[1]), "r"(a[2]), "r"(a[3]), "r"(b0), "r"(b1));
}
// round-to-nearest bf16 hi/lo split (off the hot path)
__device__ __forceinline__ void split2(float x0, float x1, uint32_t& hi, uint32_t& lo) {
    __nv_bfloat16 h0 = __float2bfloat16_rn(x0);
    __nv_bfloat16 h1 = __float2bfloat16_rn(x1);
    __nv_bfloat16 l0 = __float2bfloat16_rn(x0 - __bfloat162float(h0));
    __nv_bfloat16 l1 = __float2bfloat16_rn(x1 - __bfloat162float(h1));
    hi = (uint32_t)__bfloat16_as_ushort(h0) | ((uint32_t)__bfloat16_as_ushort(h1) << 16);
    lo = (uint32_t)__bfloat16_as_ushort(l0) | ((uint32_t)__bfloat16_as_ushort(l1) << 16);
}
// fp16 hi/lo split (off the hot path)
__device__ __forceinline__ void split2h(float x0, float x1, uint32_t& hi, uint32_t& lo) {
    __half h0 = __float2half_rn(x0);
    __half h1 = __float2half_rn(x1);
    __half l0 = __float2half_rn(x0 - __half2float(h0));
    __half l1 = __float2half_rn(x1 - __half2float(h1));
    hi = (uint32_t)__half_as_ushort(h0) | ((uint32_t)__half_as_ushort(h1) << 16);
    lo = (uint32_t)__half_as_ushort(l0) | ((uint32_t)__half_as_ushort(l1) << 16);
}
// pack two fp32 -> fp16x2 (rn), element0 in low half
__device__ __forceinline__ uint32_t pack2h(float x0, float x1) {
    uint32_t d;
    asm("cvt.rn.f16x2.f32 %0, %1, %2;" : "=r"(d) : "f"(x1), "f"(x0));
    return d;
}
__device__ __forceinline__ float ex2(float x) {
    float y;
    asm("ex2.approx.f32 %0, %1;" : "=f"(y) : "f"(x));
    return y;
}
__device__ __forceinline__ void cp16(uint32_t dst, const void* src) {
    asm volatile("cp.async.cg.shared.global [%0], [%1], 16;" :: "r"(dst), "l"(src));
}
#define CP_COMMIT() asm volatile("cp.async.commit_group;" ::: "memory")
#define CP_WAIT(n)  asm volatile("cp.async.wait_group %0;" :: "n"(n) : "memory")

// ===========================================================================
// split kernels: fp32 -> bf16 hi/lo
// ===========================================================================
__global__ void __launch_bounds__(256)
xsplit_kernel(const float* __restrict__ src)
{
    const int i = (blockIdx.x * 256 + threadIdx.x) * 4;
    float4 v = *reinterpret_cast<const float4*>(src + i);
    uint32_t h0, l0, h1, l1;
    split2(v.x, v.y, h0, l0);
    split2(v.z, v.w, h1, l1);
    *reinterpret_cast<uint2*>(g_xh + i) = make_uint2(h0, h1);
    *reinterpret_cast<uint2*>(g_xl + i) = make_uint2(l0, l1);
}
__global__ void __launch_bounds__(256)
wsplit_kernel(const float* __restrict__ Wq, const float* __restrict__ Wk,
              const float* __restrict__ Wv, const float* __restrict__ Wo)
{
    const int per = DD_ / 1024;                   // 576
    const int wsel = blockIdx.x / per;
    const int bx   = blockIdx.x % per;
    const float* src = (wsel == 0) ? Wq : (wsel == 1) ? Wk : (wsel == 2) ? Wv : Wo;
    const int i = (bx * 256 + threadIdx.x) * 4;
    float4 v = *reinterpret_cast<const float4*>(src + i);
    uint32_t h0, l0, h1, l1;
    split2(v.x, v.y, h0, l0);
    split2(v.z, v.w, h1, l1);
    const size_t o = (size_t)wsel * DD_ + i;
    *reinterpret_cast<uint2*>(g_wh + o) = make_uint2(h0, h1);
    *reinterpret_cast<uint2*>(g_wl + o) = make_uint2(l0, l1);
}

// ===========================================================================
// GEMM mainloop (bf16 pre-split inputs): acc = A @ W^T, 128x128 tile
// ===========================================================================
#define LDK_  40
#define GARR  10240
#define GEMM_SMEM (8 * GARR)        // 80KB

__device__ __forceinline__ void gemm_body(
    const __nv_bfloat16* __restrict__ Ah, const __nv_bfloat16* __restrict__ Al,
    const __nv_bfloat16* __restrict__ Wh, const __nv_bfloat16* __restrict__ Wl,
    int m0, int n0, char* smem, float acc[4][4][4])
{
    const int tid    = threadIdx.x;
    const int lane   = tid & 31;
    const int wid    = tid >> 5;
    const int warp_m = wid & 1;
    const int warp_n = wid >> 1;
    const uint32_t sb = smem_u32(smem);

#pragma unroll
    for (int i = 0; i < 4; i++)
#pragma unroll
        for (int j = 0; j < 4; j++)
#pragma unroll
            for (int e = 0; e < 4; e++) acc[i][j][e] = 0.f;

    const int grow = tid >> 1;
    const int c16  = (tid & 1) * 2;
    const __nv_bfloat16* s0 = Ah + (size_t)(m0 + grow) * D_;
    const __nv_bfloat16* s1 = Al + (size_t)(m0 + grow) * D_;
    const __nv_bfloat16* s2 = Wh + (size_t)(n0 + grow) * D_;
    const __nv_bfloat16* s3 = Wl + (size_t)(n0 + grow) * D_;

    auto issue = [&](int kc, int bsel) {
        const uint32_t dst = sb + bsel * 4 * GARR + grow * 80 + c16 * 16;
#pragma unroll
        for (int j = 0; j < 2; j++) {
            cp16(dst + j * 16,            s0 + kc + (c16 + j) * 8);
            cp16(dst + j * 16 + GARR,     s1 + kc + (c16 + j) * 8);
            cp16(dst + j * 16 + 2 * GARR, s2 + kc + (c16 + j) * 8);
            cp16(dst + j * 16 + 3 * GARR, s3 + kc + (c16 + j) * 8);
        }
    };

    const int r_a = lane & 15, c_a = (lane >> 4) * 8;
    const int r_b = (lane & 7) | ((lane >> 4) << 3);
    const int c_b = ((lane >> 3) & 1) * 8;
    const uint32_t offA = ((warp_m * 64 + r_a) * LDK_ + c_a) * 2;
    const uint32_t offB = ((warp_n * 32 + r_b) * LDK_ + c_b) * 2;

    issue(0, 0);
    CP_COMMIT();

    const int NK = D_ / 32;   // 24
    for (int it = 0; it < NK; it++) {
        if (it + 1 < NK) {
            issue((it + 1) * 32, (it + 1) & 1);
            CP_COMMIT();
            CP_WAIT(1);
        } else {
            CP_WAIT(0);
        }
        __syncthreads();

        const uint32_t bAh = sb + ((it & 1) * 4 + 0) * GARR;
        const uint32_t bAl = bAh + GARR;
        const uint32_t bWh = bAh + 2 * GARR;
        const uint32_t bWl = bAh + 3 * GARR;

#pragma unroll
        for (int ks = 0; ks < 2; ks++) {
            const uint32_t ko = ks * 32;
            uint32_t ah[4][4], al[4][4];
#pragma unroll
            for (int mt = 0; mt < 4; mt++) {
                ldsm_x4(ah[mt], bAh + offA + ko + mt * 16 * LDK_ * 2);
                ldsm_x4(al[mt], bAl + offA + ko + mt * 16 * LDK_ * 2);
            }
            uint32_t bh[8], bl[8];
#pragma unroll
            for (int g = 0; g < 2; g++) {
                ldsm_x4(&bh[g * 4], bWh + offB + ko + g * 16 * LDK_ * 2);
                ldsm_x4(&bl[g * 4], bWl + offB + ko + g * 16 * LDK_ * 2);
            }
#pragma unroll
            for (int mt = 0; mt < 4; mt++)
#pragma unroll
                for (int nt = 0; nt < 4; nt++) {
                    mma16816(acc[mt][nt], ah[mt], bh[nt * 2], bh[nt * 2 + 1]);
                    mma16816(acc[mt][nt], ah[mt], bl[nt * 2], bl[nt * 2 + 1]);
                    mma16816(acc[mt][nt], al[mt], bh[nt * 2], bh[nt * 2 + 1]);
                }
        }
        __syncthreads();
    }
}

// ===========================================================================
// fused QKV GEMM: proj + bias + (L2 norm + scale for q,k) + split store.
// q,k -> bf16 split; v -> fp16 split.
// ===========================================================================
__global__ void __launch_bounds__(256, 2)
qkv_gemm(const float* __restrict__ bq, const float* __restrict__ bk,
         const float* __restrict__ bv, const float* __restrict__ ls)
{
    extern __shared__ char smem[];
    const int wsel = blockIdx.x / 6;
    const int n0   = (blockIdx.x % 6) * 128;
    const int m0   = blockIdx.y * 128;

    float acc[4][4][4];
    gemm_body(g_xh, g_xl, g_wh + (size_t)wsel * DD_, g_wl + (size_t)wsel * DD_,
              m0, n0, smem, acc);

    const int tid  = threadIdx.x;
    const int lane = tid & 31;
    const int wid  = tid >> 5;
    const int warp_m = wid & 1, warp_n = wid >> 1;

    const float* bias = (wsel == 0) ? bq : (wsel == 1) ? bk : bv;

    float2 bv2[4];
#pragma unroll
    for (int nt = 0; nt < 4; nt++)
        bv2[nt] = *reinterpret_cast<const float2*>(
            &bias[n0 + warp_n * 32 + nt * 8 + 2 * (lane & 3)]);
#pragma unroll
    for (int mt = 0; mt < 4; mt++)
#pragma unroll
        for (int nt = 0; nt < 4; nt++) {
            acc[mt][nt][0] += bv2[nt].x; acc[mt][nt][1] += bv2[nt].y;
            acc[mt][nt][2] += bv2[nt].x; acc[mt][nt][3] += bv2[nt].y;
        }

    __syncthreads();
    float* sq = reinterpret_cast<float*>(smem);   // [128][4]

    if (wsel < 2) {
#pragma unroll
        for (int mt = 0; mt < 4; mt++)
#pragma unroll
            for (int half = 0; half < 2; half++) {
                const int r = warp_m * 64 + mt * 16 + (lane >> 2) + half * 8;
                float p = 0.f;
#pragma unroll
                for (int nt = 0; nt < 4; nt++) {
                    const float a = acc[mt][nt][half * 2], bvv = acc[mt][nt][half * 2 + 1];
                    p += a * a + bvv * bvv;
                }
                p += __shfl_xor_sync(0xffffffffu, p, 1);
                p += __shfl_xor_sync(0xffffffffu, p, 2);
                if ((lane & 3) == 0) sq[r * 4 + warp_n] = p;
            }
        __syncthreads();
    }

    float scl = 1.f;
    if (wsel == 0) {
        const int hh = 2 * (blockIdx.x % 6) + (warp_n >> 1);
        scl = __expf(fminf(ls[hh], 4.6051701859880914f)) * LOG2E_;
    }

#pragma unroll
    for (int mt = 0; mt < 4; mt++) {
#pragma unroll
        for (int half = 0; half < 2; half++) {
            const int r = warp_m * 64 + mt * 16 + (lane >> 2) + half * 8;
            float inv = 1.f;
            if (wsel < 2) {
                const float s2 = sq[r * 4 + (warp_n & 2)] + sq[r * 4 + (warp_n & 2) + 1];
                inv = scl / fmaxf(sqrtf(s2), 1e-12f);
            }
            const int m  = m0 + r;
            const int bb = m >> 11, ss = m & (S_ - 1);
#pragma unroll
            for (int nt = 0; nt < 4; nt++) {
                const int n  = n0 + warp_n * 32 + nt * 8 + 2 * (lane & 3);
                const int hh = n >> 6, dd = n & 63;
                const size_t idx = (((size_t)(bb * H_ + hh)) * S_ + ss) * DH_ + dd;
                uint32_t hi, lo;
                if (wsel == 2) {
                    split2h(acc[mt][nt][half * 2], acc[mt][nt][half * 2 + 1], hi, lo);
                    *reinterpret_cast<uint32_t*>(&g_vh[idx]) = hi;
                    *reinterpret_cast<uint32_t*>(&g_vl[idx]) = lo;
                } else {
                    split2(acc[mt][nt][half * 2] * inv, acc[mt][nt][half * 2 + 1] * inv, hi, lo);
                    __nv_bfloat16* dh = (wsel == 0) ? g_qh : g_kh;
                    __nv_bfloat16* dl = (wsel == 0) ? g_ql : g_kl;
                    *reinterpret_cast<uint32_t*>(&dh[idx]) = hi;
                    *reinterpret_cast<uint32_t*>(&dl[idx]) = lo;
                }
            }
        }
    }
}

// output GEMM: ctx(split) @ Wo^T + bo -> d_out
__global__ void __launch_bounds__(256, 2)
o_gemm(const float* __restrict__ bo, float* __restrict__ out)
{
    extern __shared__ char smem[];
    const int n0 = blockIdx.x * 128;
    const int m0 = blockIdx.y * 128;

    float acc[4][4][4];
    gemm_body(g_ch, g_cl, g_wh + 3 * (size_t)DD_, g_wl + 3 * (size_t)DD_,
              m0, n0, smem, acc);

    const int lane = threadIdx.x & 31;
    const int wid  = threadIdx.x >> 5;
    const int warp_m = wid & 1, warp_n = wid >> 1;
#pragma unroll
    for (int mt = 0; mt < 4; mt++) {
#pragma unroll
        for (int nt = 0; nt < 4; nt++) {
            const int n = n0 + warp_n * 32 + nt * 8 + 2 * (lane & 3);
            const float2 bv2 = *reinterpret_cast<const float2*>(&bo[n]);
#pragma unroll
            for (int half = 0; half < 2; half++) {
                const int m = m0 + warp_m * 64 + mt * 16 + (lane >> 2) + half * 8;
                float2 o;
                o.x = acc[mt][nt][half * 2 + 0] + bv2.x;
                o.y = acc[mt][nt][half * 2 + 1] + bv2.y;
                *reinterpret_cast<float2*>(out + (size_t)m * D_ + n) = o;
            }
        }
    }
}

// ===========================================================================
// HMMA flash attention, fixed-max softmax.
// QK: bf16x3 (precision feeds exp). PV: fp16 P (single) x fp16 V (hi/lo)
// -> 2 MMAs per og (was 3). P-quant error ~1.5e-4 (R8-calibrated).
// ===========================================================================
#define ABUF   9216
#define ATTN_SMEM (12 * ABUF)      // 3 buffers x {Kh,Kl,Vh,Vl}

__global__ void __launch_bounds__(256, 2)
attn_mma(const float* __restrict__ ls)
{
    extern __shared__ char sm[];
    const uint32_t sbase = smem_u32(sm);
    const int tid  = threadIdx.x;
    const int lane = tid & 31;
    const int wid  = tid >> 5;
    const int bh   = blockIdx.y;
    const int h    = bh % H_;
    const int b    = bh / H_;
    const int q0   = blockIdx.x * 128;
    const size_t base = (size_t)bh * S_ * DH_;
    const float Mfix = __expf(fminf(ls[h], 4.6051701859880914f)) * LOG2E_;

    // stage Q hi/lo into smem, build A-fragments, release
    {
        const __nv_bfloat16* gq0 = g_qh + base + (size_t)q0 * DH_;
        const __nv_bfloat16* gq1 = g_ql + base + (size_t)q0 * DH_;
#pragma unroll
        for (int i = 0; i < 8; i++) {
            const int arr = i >> 2;
            const int idx = ((i & 3) << 8) + tid;
            const int row = idx >> 3, c = idx & 7;
            const uint4 v = *reinterpret_cast<const uint4*>(
                (arr ? gq1 : gq0) + row * DH_ + c * 8);
            *reinterpret_cast<uint4*>(sm + arr * 18432 + row * 144 + c * 16) = v;
        }
    }
    __syncthreads();
    uint32_t qfh[4][4], qfl[4][4];
    {
        const uint32_t qa = sbase + (wid * 16 + (lane & 15)) * 144 + (lane >> 4) * 16;
#pragma unroll
        for (int kt = 0; kt < 4; kt++) {
            ldsm_x4(qfh[kt], qa + kt * 32);
            ldsm_x4(qfl[kt], qa + 18432 + kt * 32);
        }
    }
    __syncthreads();

    float o[8][4];
#pragma unroll
    for (int nt = 0; nt < 8; nt++)
#pragma unroll
        for (int e = 0; e < 4; e++) o[nt][e] = 0.f;
    float l0 = 0.f, l1 = 0.f;

    const uint32_t lofs = (lane & 15) * 144 + (lane >> 4) * 16;

    const __nv_bfloat16* gkh = g_kh + base;
    const __nv_bfloat16* gkl = g_kl + base;
    const __half*        gvh = g_vh + base;
    const __half*        gvl = g_vl + base;

    auto issue = [&](int it, int bsel) {
        const int koff = it * 64 * DH_;
#pragma unroll
        for (int i = 0; i < 8; i++) {
            const int arr = i >> 1;
            const int idx = ((i & 1) << 8) + tid;
            const int row = idx >> 3, c = idx & 7;
            const void* gp;
            if      (arr == 0) gp = gkh + koff + row * DH_ + c * 8;
            else if (arr == 1) gp = gkl + koff + row * DH_ + c * 8;
            else if (arr == 2) gp = gvh + koff + row * DH_ + c * 8;
            else               gp = gvl + koff + row * DH_ + c * 8;
            cp16(sbase + (bsel * 4 + arr) * ABUF + row * 144 + c * 16, gp);
        }
    };

    issue(0, 0); CP_COMMIT();
    issue(1, 1); CP_COMMIT();

    const int NIT = S_ / 64;   // 32
    for (int it = 0; it < NIT; it++) {
        if (it + 1 < NIT) { CP_WAIT(1); } else { CP_WAIT(0); }
        __syncthreads();
        if (it + 2 < NIT) { issue(it + 2, (it + 2) % 3); CP_COMMIT(); }

        const uint32_t Kh = sbase + ((it % 3) * 4) * ABUF;
        const uint32_t Kl = Kh + ABUF;
        const uint32_t Vh = Kh + 2 * ABUF;
        const uint32_t Vl = Kh + 3 * ABUF;

        // QK for one 16-key block g -> s0[4], s1[4] (logits - M)
        auto qk_block = [&](int g, float* s0p, float* s1p) {
#pragma unroll
            for (int e = 0; e < 4; e++) { s0p[e] = -Mfix; s1p[e] = -Mfix; }
#pragma unroll
            for (int kt = 0; kt < 4; kt++) {
                uint32_t kf[4], lf[4];
                ldsm_x4(kf, Kh + lofs + g * 16 * 144 + kt * 32);
                ldsm_x4(lf, Kl + lofs + g * 16 * 144 + kt * 32);
                mma16816(s0p, qfh[kt], kf[0], kf[2]);
                mma16816(s0p, qfh[kt], lf[0], lf[2]);
                mma16816(s0p, qfl[kt], kf[0], kf[2]);
                mma16816(s1p, qfh[kt], kf[1], kf[3]);
                mma16816(s1p, qfh[kt], lf[1], lf[3]);
                mma16816(s1p, qfl[kt], kf[1], kf[3]);
            }
        };
        // exp2 + fp16 pack + l accumulation
        auto exppack = [&](float* s0p, float* s1p, uint32_t* ph) {
#pragma unroll
            for (int e = 0; e < 4; e++) { s0p[e] = ex2(s0p[e]); s1p[e] = ex2(s1p[e]); }
            l0 += s0p[0] + s0p[1] + s1p[0] + s1p[1];
            l1 += s0p[2] + s0p[3] + s1p[2] + s1p[3];
            ph[0] = pack2h(s0p[0], s0p[1]);
            ph[1] = pack2h(s0p[2], s0p[3]);
            ph[2] = pack2h(s1p[0], s1p[1]);
            ph[3] = pack2h(s1p[2], s1p[3]);
        };
        // PV of block g: o += P_g(fp16) @ (Vh + Vl)  -- 2 MMAs per og
        auto pv_block = [&](int g, const uint32_t* ph) {
#pragma unroll
            for (int og = 0; og < 4; og++) {
                uint32_t vf[4], wf[4];
                ldsm_x4_t(vf, Vh + lofs + g * 16 * 144 + og * 32);
                ldsm_x4_t(wf, Vl + lofs + g * 16 * 144 + og * 32);
                mma16816h(o[2 * og],     ph, vf[0], vf[1]);
                mma16816h(o[2 * og],     ph, wf[0], wf[1]);
                mma16816h(o[2 * og + 1], ph, vf[2], vf[3]);
                mma16816h(o[2 * og + 1], ph, wf[2], wf[3]);
            }
        };

        float sA0[4], sA1[4], sB0[4], sB1[4];
        uint32_t pA[4], pB[4];

        qk_block(0, sA0, sA1);
        exppack(sA0, sA1, pA);

        qk_block(1, sB0, sB1);
        pv_block(0, pA);
        exppack(sB0, sB1, pB);

        qk_block(2, sA0, sA1);
        pv_block(1, pB);
        exppack(sA0, sA1, pA);

        qk_block(3, sB0, sB1);
        pv_block(2, pA);
        exppack(sB0, sB1, pB);

        pv_block(3, pB);
    }

    // epilogue: reduce l across quad lanes once, normalize, store bf16 splits
    l0 += __shfl_xor_sync(0xffffffffu, l0, 1);
    l0 += __shfl_xor_sync(0xffffffffu, l0, 2);
    l1 += __shfl_xor_sync(0xffffffffu, l1, 1);
    l1 += __shfl_xor_sync(0xffffffffu, l1, 2);
    const float inv0 = 1.f / l0;
    const float inv1 = 1.f / l1;
    const int row0 = q0 + wid * 16 + (lane >> 2);
    const int col0 = h * DH_ + 2 * (lane & 3);
    const size_t p0 = ((size_t)b * S_ + row0) * D_ + col0;
    const size_t p1 = p0 + 8 * D_;
#pragma unroll
    for (int nt = 0; nt < 8; nt++) {
        uint32_t hi, lo;
        split2(o[nt][0] * inv0, o[nt][1] * inv0, hi, lo);
        *reinterpret_cast<uint32_t*>(g_ch + p0 + nt * 8) = hi;
        *reinterpret_cast<uint32_t*>(g_cl + p0 + nt * 8) = lo;
        split2(o[nt][2] * inv1, o[nt][3] * inv1, hi, lo);
        *reinterpret_cast<uint32_t*>(g_ch + p1 + nt * 8) = hi;
        *reinterpret_cast<uint32_t*>(g_cl + p1 + nt * 8) = lo;
    }
}

// ---------------------------------------------------------------------------
// Launch
// ---------------------------------------------------------------------------
extern "C" void kernel_launch(void* const* d_in, const int* in_sizes, int n_in,
                              void* d_out, int out_size)
{
    const float* x  = (const float*)d_in[0];
    const float* Wq = (const float*)d_in[1];
    const float* bq = (const float*)d_in[2];
    const float* Wk = (const float*)d_in[3];
    const float* bk = (const float*)d_in[4];
    const float* Wv = (const float*)d_in[5];
    const float* bv = (const float*)d_in[6];
    const float* Wo = (const float*)d_in[7];
    const float* bo = (const float*)d_in[8];
    const float* ls = (const float*)d_in[9];
    float* out = (float*)d_out;

    xsplit_kernel<<<(M_ * D_) / 1024, 256>>>(x);
    wsplit_kernel<<<4 * (DD_ / 1024), 256>>>(Wq, Wk, Wv, Wo);

    cudaFuncSetAttribute(qkv_gemm, cudaFuncAttributeMaxDynamicSharedMemorySize, GEMM_SMEM);
    cudaFuncSetAttribute(o_gemm,   cudaFuncAttributeMaxDynamicSharedMemorySize, GEMM_SMEM);
    cudaFuncSetAttribute(attn_mma, cudaFuncAttributeMaxDynamicSharedMemorySize, ATTN_SMEM);

    qkv_gemm<<<dim3(18, M_ / 128), 256, GEMM_SMEM>>>(bq, bk, bv, ls);

    attn_mma<<<dim3(S_ / 128, B_ * H_), 256, ATTN_SMEM>>>(ls);

    o_gemm<<<dim3(D_ / 128, M_ / 128), 256, GEMM_SMEM>>>(bo, out);
}

// round 12
// speedup vs baseline: 1.3411x; 1.2358x over previous
#include <cuda_runtime.h>
#include <cuda_bf16.h>
#include <cuda_fp16.h>
#include <math.h>
#include <cstdint>

#define B_  4
#define S_  2048
#define D_  768
#define H_  12
#define DH_ 64
#define M_  (B_*S_)          // 8192
#define NROWS_ (B_*H_*S_)    // 98304
#define QKVN_ (NROWS_*DH_)   // 6291456
#define DD_  (D_*D_)         // 589824
#define LOG2E_ 1.4426950408889634f

// Scratch (allocation-free: static __device__ globals)
__device__ __nv_bfloat16 g_xh[M_*D_],  g_xl[M_*D_];
__device__ __nv_bfloat16 g_wh[4*DD_],  g_wl[4*DD_];
__device__ __half        g_qh[QKVN_],  g_ql[QKVN_];     // q: fp16 split (prescaled)
__device__ __half        g_kh[QKVN_];                   // k: single fp16
__device__ __half        g_vh[QKVN_];                   // v: single fp16
__device__ __nv_bfloat16 g_ch[M_*D_],  g_cl[M_*D_];

// ===========================================================================
// Helpers
// ===========================================================================
__device__ __forceinline__ uint32_t smem_u32(const void* p) {
    uint32_t r;
    asm("{ .reg .u64 t; cvta.to.shared.u64 t, %1; cvt.u32.u64 %0, t; }"
        : "=r"(r) : "l"(p));
    return r;
}
__device__ __forceinline__ void ldsm_x4(uint32_t* r, uint32_t addr) {
    asm volatile("ldmatrix.sync.aligned.m8n8.x4.shared.b16 {%0,%1,%2,%3}, [%4];"
                 : "=r"(r[0]), "=r"(r[1]), "=r"(r[2]), "=r"(r[3]) : "r"(addr));
}
__device__ __forceinline__ void ldsm_x4_t(uint32_t* r, uint32_t addr) {
    asm volatile("ldmatrix.sync.aligned.m8n8.x4.trans.shared.b16 {%0,%1,%2,%3}, [%4];"
                 : "=r"(r[0]), "=r"(r[1]), "=r"(r[2]), "=r"(r[3]) : "r"(addr));
}
// bf16 in, fp32 accum
__device__ __forceinline__ void mma16816(float* d, const uint32_t* a,
                                         uint32_t b0, uint32_t b1) {
    asm volatile(
        "mma.sync.aligned.m16n8k16.row.col.f32.bf16.bf16.f32 "
        "{%0,%1,%2,%3}, {%4,%5,%6,%7}, {%8,%9}, {%0,%1,%2,%3};"
        : "+f"(d[0]), "+f"(d[1]), "+f"(d[2]), "+f"(d[3])
        : "r"(a[0]), "r"(a[1]), "r"(a[2]), "r"(a[3]), "r"(b0), "r"(b1));
}
// fp16 in, fp32 accum
__device__ __forceinline__ void mma16816h(float* d, const uint32_t* a,
                                          uint32_t b0, uint32_t b1) {
    asm volatile(
        "mma.sync.aligned.m16n8k16.row.col.f32.f16.f16.f32 "
        "{%0,%1,%2,%3}, {%4,%5,%6,%7}, {%8,%9}, {%0,%1,%2,%3};"
        : "+f"(d[0]), "+f"(d[1]), "+f"(d[2]), "+f"(d[3])
        : "r"(a[0]), "r"(a[1]), "r"(a[2]), "r"(a[3]), "r"(b0), "r"(b1));
}
// round-to-nearest bf16 hi/lo split (off the hot path)
__device__ __forceinline__ void split2(float x0, float x1, uint32_t& hi, uint32_t& lo) {
    __nv_bfloat16 h0 = __float2bfloat16_rn(x0);
    __nv_bfloat16 h1 = __float2bfloat16_rn(x1);
    __nv_bfloat16 l0 = __float2bfloat16_rn(x0 - __bfloat162float(h0));
    __nv_bfloat16 l1 = __float2bfloat16_rn(x1 - __bfloat162float(h1));
    hi = (uint32_t)__bfloat16_as_ushort(h0) | ((uint32_t)__bfloat16_as_ushort(h1) << 16);
    lo = (uint32_t)__bfloat16_as_ushort(l0) | ((uint32_t)__bfloat16_as_ushort(l1) << 16);
}
// fp16 hi/lo split (off the hot path)
__device__ __forceinline__ void split2h(float x0, float x1, uint32_t& hi, uint32_t& lo) {
    __half h0 = __float2half_rn(x0);
    __half h1 = __float2half_rn(x1);
    __half l0 = __float2half_rn(x0 - __half2float(h0));
    __half l1 = __float2half_rn(x1 - __half2float(h1));
    hi = (uint32_t)__half_as_ushort(h0) | ((uint32_t)__half_as_ushort(h1) << 16);
    lo = (uint32_t)__half_as_ushort(l0) | ((uint32_t)__half_as_ushort(l1) << 16);
}
// pack two fp32 -> fp16x2 (rn), element0 in low half
__device__ __forceinline__ uint32_t pack2h(float x0, float x1) {
    uint32_t d;
    asm("cvt.rn.f16x2.f32 %0, %1, %2;" : "=r"(d) : "f"(x1), "f"(x0));
    return d;
}
__device__ __forceinline__ float ex2(float x) {
    float y;
    asm("ex2.approx.f32 %0, %1;" : "=f"(y) : "f"(x));
    return y;
}
__device__ __forceinline__ void cp16(uint32_t dst, const void* src) {
    asm volatile("cp.async.cg.shared.global [%0], [%1], 16;" :: "r"(dst), "l"(src));
}
#define CP_COMMIT() asm volatile("cp.async.commit_group;" ::: "memory")
#define CP_WAIT(n)  asm volatile("cp.async.wait_group %0;" :: "n"(n) : "memory")

// ===========================================================================
// split kernels: fp32 -> bf16 hi/lo
// ===========================================================================
__global__ void __launch_bounds__(256)
xsplit_kernel(const float* __restrict__ src)
{
    const int i = (blockIdx.x * 256 + threadIdx.x) * 4;
    float4 v = *reinterpret_cast<const float4*>(src + i);
    uint32_t h0, l0, h1, l1;
    split2(v.x, v.y, h0, l0);
    split2(v.z, v.w, h1, l1);
    *reinterpret_cast<uint2*>(g_xh + i) = make_uint2(h0, h1);
    *reinterpret_cast<uint2*>(g_xl + i) = make_uint2(l0, l1);
}
__global__ void __launch_bounds__(256)
wsplit_kernel(const float* __restrict__ Wq, const float* __restrict__ Wk,
              const float* __restrict__ Wv, const float* __restrict__ Wo)
{
    const int per = DD_ / 1024;                   // 576
    const int wsel = blockIdx.x / per;
    const int bx   = blockIdx.x % per;
    const float* src = (wsel == 0) ? Wq : (wsel == 1) ? Wk : (wsel == 2) ? Wv : Wo;
    const int i = (bx * 256 + threadIdx.x) * 4;
    float4 v = *reinterpret_cast<const float4*>(src + i);
    uint32_t h0, l0, h1, l1;
    split2(v.x, v.y, h0, l0);
    split2(v.z, v.w, h1, l1);
    const size_t o = (size_t)wsel * DD_ + i;
    *reinterpret_cast<uint2*>(g_wh + o) = make_uint2(h0, h1);
    *reinterpret_cast<uint2*>(g_wl + o) = make_uint2(l0, l1);
}

// ===========================================================================
// GEMM mainloop (bf16 pre-split inputs): acc = A @ W^T, 128x128 tile
// ===========================================================================
#define LDK_  40
#define GARR  10240
#define GEMM_SMEM (8 * GARR)        // 80KB

__device__ __forceinline__ void gemm_body(
    const __nv_bfloat16* __restrict__ Ah, const __nv_bfloat16* __restrict__ Al,
    const __nv_bfloat16* __restrict__ Wh, const __nv_bfloat16* __restrict__ Wl,
    int m0, int n0, char* smem, float acc[4][4][4])
{
    const int tid    = threadIdx.x;
    const int lane   = tid & 31;
    const int wid    = tid >> 5;
    const int warp_m = wid & 1;
    const int warp_n = wid >> 1;
    const uint32_t sb = smem_u32(smem);

#pragma unroll
    for (int i = 0; i < 4; i++)
#pragma unroll
        for (int j = 0; j < 4; j++)
#pragma unroll
            for (int e = 0; e < 4; e++) acc[i][j][e] = 0.f;

    const int grow = tid >> 1;
    const int c16  = (tid & 1) * 2;
    const __nv_bfloat16* s0 = Ah + (size_t)(m0 + grow) * D_;
    const __nv_bfloat16* s1 = Al + (size_t)(m0 + grow) * D_;
    const __nv_bfloat16* s2 = Wh + (size_t)(n0 + grow) * D_;
    const __nv_bfloat16* s3 = Wl + (size_t)(n0 + grow) * D_;

    auto issue = [&](int kc, int bsel) {
        const uint32_t dst = sb + bsel * 4 * GARR + grow * 80 + c16 * 16;
#pragma unroll
        for (int j = 0; j < 2; j++) {
            cp16(dst + j * 16,            s0 + kc + (c16 + j) * 8);
            cp16(dst + j * 16 + GARR,     s1 + kc + (c16 + j) * 8);
            cp16(dst + j * 16 + 2 * GARR, s2 + kc + (c16 + j) * 8);
            cp16(dst + j * 16 + 3 * GARR, s3 + kc + (c16 + j) * 8);
        }
    };

    const int r_a = lane & 15, c_a = (lane >> 4) * 8;
    const int r_b = (lane & 7) | ((lane >> 4) << 3);
    const int c_b = ((lane >> 3) & 1) * 8;
    const uint32_t offA = ((warp_m * 64 + r_a) * LDK_ + c_a) * 2;
    const uint32_t offB = ((warp_n * 32 + r_b) * LDK_ + c_b) * 2;

    issue(0, 0);
    CP_COMMIT();

    const int NK = D_ / 32;   // 24
    for (int it = 0; it < NK; it++) {
        if (it + 1 < NK) {
            issue((it + 1) * 32, (it + 1) & 1);
            CP_COMMIT();
            CP_WAIT(1);
        } else {
            CP_WAIT(0);
        }
        __syncthreads();

        const uint32_t bAh = sb + ((it & 1) * 4 + 0) * GARR;
        const uint32_t bAl = bAh + GARR;
        const uint32_t bWh = bAh + 2 * GARR;
        const uint32_t bWl = bAh + 3 * GARR;

#pragma unroll
        for (int ks = 0; ks < 2; ks++) {
            const uint32_t ko = ks * 32;
            uint32_t ah[4][4], al[4][4];
#pragma unroll
            for (int mt = 0; mt < 4; mt++) {
                ldsm_x4(ah[mt], bAh + offA + ko + mt * 16 * LDK_ * 2);
                ldsm_x4(al[mt], bAl + offA + ko + mt * 16 * LDK_ * 2);
            }
            uint32_t bh[8], bl[8];
#pragma unroll
            for (int g = 0; g < 2; g++) {
                ldsm_x4(&bh[g * 4], bWh + offB + ko + g * 16 * LDK_ * 2);
                ldsm_x4(&bl[g * 4], bWl + offB + ko + g * 16 * LDK_ * 2);
            }
#pragma unroll
            for (int mt = 0; mt < 4; mt++)
#pragma unroll
                for (int nt = 0; nt < 4; nt++) {
                    mma16816(acc[mt][nt], ah[mt], bh[nt * 2], bh[nt * 2 + 1]);
                    mma16816(acc[mt][nt], ah[mt], bl[nt * 2], bl[nt * 2 + 1]);
                    mma16816(acc[mt][nt], al[mt], bh[nt * 2], bh[nt * 2 + 1]);
                }
        }
        __syncthreads();
    }
}

// ===========================================================================
// fused QKV GEMM: proj + bias + (L2 norm + scale for q,k) + store.
// q -> fp16 split (prescaled by exp(min(ls,ln100))*log2e); k,v -> single fp16.
// ===========================================================================
__global__ void __launch_bounds__(256, 2)
qkv_gemm(const float* __restrict__ bq, const float* __restrict__ bk,
         const float* __restrict__ bv, const float* __restrict__ ls)
{
    extern __shared__ char smem[];
    const int wsel = blockIdx.x / 6;
    const int n0   = (blockIdx.x % 6) * 128;
    const int m0   = blockIdx.y * 128;

    float acc[4][4][4];
    gemm_body(g_xh, g_xl, g_wh + (size_t)wsel * DD_, g_wl + (size_t)wsel * DD_,
              m0, n0, smem, acc);

    const int tid  = threadIdx.x;
    const int lane = tid & 31;
    const int wid  = tid >> 5;
    const int warp_m = wid & 1, warp_n = wid >> 1;

    const float* bias = (wsel == 0) ? bq : (wsel == 1) ? bk : bv;

    float2 bv2[4];
#pragma unroll
    for (int nt = 0; nt < 4; nt++)
        bv2[nt] = *reinterpret_cast<const float2*>(
            &bias[n0 + warp_n * 32 + nt * 8 + 2 * (lane & 3)]);
#pragma unroll
    for (int mt = 0; mt < 4; mt++)
#pragma unroll
        for (int nt = 0; nt < 4; nt++) {
            acc[mt][nt][0] += bv2[nt].x; acc[mt][nt][1] += bv2[nt].y;
            acc[mt][nt][2] += bv2[nt].x; acc[mt][nt][3] += bv2[nt].y;
        }

    __syncthreads();
    float* sq = reinterpret_cast<float*>(smem);   // [128][4]

    if (wsel < 2) {
#pragma unroll
        for (int mt = 0; mt < 4; mt++)
#pragma unroll
            for (int half = 0; half < 2; half++) {
                const int r = warp_m * 64 + mt * 16 + (lane >> 2) + half * 8;
                float p = 0.f;
#pragma unroll
                for (int nt = 0; nt < 4; nt++) {
                    const float a = acc[mt][nt][half * 2], bvv = acc[mt][nt][half * 2 + 1];
                    p += a * a + bvv * bvv;
                }
                p += __shfl_xor_sync(0xffffffffu, p, 1);
                p += __shfl_xor_sync(0xffffffffu, p, 2);
                if ((lane & 3) == 0) sq[r * 4 + warp_n] = p;
            }
        __syncthreads();
    }

    float scl = 1.f;
    if (wsel == 0) {
        const int hh = 2 * (blockIdx.x % 6) + (warp_n >> 1);
        scl = __expf(fminf(ls[hh], 4.6051701859880914f)) * LOG2E_;
    }

#pragma unroll
    for (int mt = 0; mt < 4; mt++) {
#pragma unroll
        for (int half = 0; half < 2; half++) {
            const int r = warp_m * 64 + mt * 16 + (lane >> 2) + half * 8;
            float inv = 1.f;
            if (wsel < 2) {
                const float s2 = sq[r * 4 + (warp_n & 2)] + sq[r * 4 + (warp_n & 2) + 1];
                inv = scl / fmaxf(sqrtf(s2), 1e-12f);
            }
            const int m  = m0 + r;
            const int bb = m >> 11, ss = m & (S_ - 1);
#pragma unroll
            for (int nt = 0; nt < 4; nt++) {
                const int n  = n0 + warp_n * 32 + nt * 8 + 2 * (lane & 3);
                const int hh = n >> 6, dd = n & 63;
                const size_t idx = (((size_t)(bb * H_ + hh)) * S_ + ss) * DH_ + dd;
                const float a0 = acc[mt][nt][half * 2]     * inv;
                const float a1 = acc[mt][nt][half * 2 + 1] * inv;
                if (wsel == 0) {
                    uint32_t hi, lo;
                    split2h(a0, a1, hi, lo);
                    *reinterpret_cast<uint32_t*>(&g_qh[idx]) = hi;
                    *reinterpret_cast<uint32_t*>(&g_ql[idx]) = lo;
                } else if (wsel == 1) {
                    *reinterpret_cast<uint32_t*>(&g_kh[idx]) = pack2h(a0, a1);
                } else {
                    *reinterpret_cast<uint32_t*>(&g_vh[idx]) = pack2h(a0, a1);
                }
            }
        }
    }
}

// output GEMM: ctx(split) @ Wo^T + bo -> d_out
__global__ void __launch_bounds__(256, 2)
o_gemm(const float* __restrict__ bo, float* __restrict__ out)
{
    extern __shared__ char smem[];
    const int n0 = blockIdx.x * 128;
    const int m0 = blockIdx.y * 128;

    float acc[4][4][4];
    gemm_body(g_ch, g_cl, g_wh + 3 * (size_t)DD_, g_wl + 3 * (size_t)DD_,
              m0, n0, smem, acc);

    const int lane = threadIdx.x & 31;
    const int wid  = threadIdx.x >> 5;
    const int warp_m = wid & 1, warp_n = wid >> 1;
#pragma unroll
    for (int mt = 0; mt < 4; mt++) {
#pragma unroll
        for (int nt = 0; nt < 4; nt++) {
            const int n = n0 + warp_n * 32 + nt * 8 + 2 * (lane & 3);
            const float2 bv2 = *reinterpret_cast<const float2*>(&bo[n]);
#pragma unroll
            for (int half = 0; half < 2; half++) {
                const int m = m0 + warp_m * 64 + mt * 16 + (lane >> 2) + half * 8;
                float2 o;
                o.x = acc[mt][nt][half * 2 + 0] + bv2.x;
                o.y = acc[mt][nt][half * 2 + 1] + bv2.y;
                *reinterpret_cast<float2*>(out + (size_t)m * D_ + n) = o;
            }
        }
    }
}

// ===========================================================================
// HMMA flash attention, fixed-max softmax, all-fp16 tensor path.
// QK: (qh+ql) x kh -- 2 MMAs (k-quant err ~3e-4 on P, rms).
// PV: P(fp16) x vh -- 1 MMA (V-quant err ~1.5e-4, calibrated model).
// KV smem: only {Kh, Vh} -- half the cp.async/ldsm of R11.
// ===========================================================================
#define ABUF   9216
#define ATTN_SMEM (6 * ABUF)       // 3 stages x {Kh, Vh}

__global__ void __launch_bounds__(256, 2)
attn_mma(const float* __restrict__ ls)
{
    extern __shared__ char sm[];
    const uint32_t sbase = smem_u32(sm);
    const int tid  = threadIdx.x;
    const int lane = tid & 31;
    const int wid  = tid >> 5;
    const int bh   = blockIdx.y;
    const int h    = bh % H_;
    const int b    = bh / H_;
    const int q0   = blockIdx.x * 128;
    const size_t base = (size_t)bh * S_ * DH_;
    const float Mfix = __expf(fminf(ls[h], 4.6051701859880914f)) * LOG2E_;

    // stage Q hi/lo (fp16) into smem, build A-fragments, release
    {
        const __half* gq0 = g_qh + base + (size_t)q0 * DH_;
        const __half* gq1 = g_ql + base + (size_t)q0 * DH_;
#pragma unroll
        for (int i = 0; i < 8; i++) {
            const int arr = i >> 2;
            const int idx = ((i & 3) << 8) + tid;
            const int row = idx >> 3, c = idx & 7;
            const uint4 v = *reinterpret_cast<const uint4*>(
                (arr ? gq1 : gq0) + row * DH_ + c * 8);
            *reinterpret_cast<uint4*>(sm + arr * 18432 + row * 144 + c * 16) = v;
        }
    }
    __syncthreads();
    uint32_t qfh[4][4], qfl[4][4];
    {
        const uint32_t qa = sbase + (wid * 16 + (lane & 15)) * 144 + (lane >> 4) * 16;
#pragma unroll
        for (int kt = 0; kt < 4; kt++) {
            ldsm_x4(qfh[kt], qa + kt * 32);
            ldsm_x4(qfl[kt], qa + 18432 + kt * 32);
        }
    }
    __syncthreads();

    float o[8][4];
#pragma unroll
    for (int nt = 0; nt < 8; nt++)
#pragma unroll
        for (int e = 0; e < 4; e++) o[nt][e] = 0.f;
    float l0 = 0.f, l1 = 0.f;

    const uint32_t lofs = (lane & 15) * 144 + (lane >> 4) * 16;

    const __half* gkh = g_kh + base;
    const __half* gvh = g_vh + base;

    // KV tile: 2 arrays x 64 rows x 128B = 1024 chunks of 16B, 4/thread
    auto issue = [&](int it, int bsel) {
        const int koff = it * 64 * DH_;
#pragma unroll
        for (int i = 0; i < 4; i++) {
            const int idx = (i << 8) + tid;        // 0..1023
            const int arr = idx >> 9;              // 0..1
            const int row = (idx >> 3) & 63;
            const int c   = idx & 7;
            const __half* gp = (arr == 0 ? gkh : gvh) + koff + row * DH_ + c * 8;
            cp16(sbase + (bsel * 2 + arr) * ABUF + row * 144 + c * 16, gp);
        }
    };

    issue(0, 0); CP_COMMIT();
    issue(1, 1); CP_COMMIT();

    const int NIT = S_ / 64;   // 32
    for (int it = 0; it < NIT; it++) {
        if (it + 1 < NIT) { CP_WAIT(1); } else { CP_WAIT(0); }
        __syncthreads();
        if (it + 2 < NIT) { issue(it + 2, (it + 2) % 3); CP_COMMIT(); }

        const uint32_t Kh = sbase + ((it % 3) * 2) * ABUF;
        const uint32_t Vh = Kh + ABUF;

        // QK for one 16-key block g -> s0[4], s1[4] (logits - M)
        auto qk_block = [&](int g, float* s0p, float* s1p) {
#pragma unroll
            for (int e = 0; e < 4; e++) { s0p[e] = -Mfix; s1p[e] = -Mfix; }
#pragma unroll
            for (int kt = 0; kt < 4; kt++) {
                uint32_t kf[4];
                ldsm_x4(kf, Kh + lofs + g * 16 * 144 + kt * 32);
                mma16816h(s0p, qfh[kt], kf[0], kf[2]);
                mma16816h(s0p, qfl[kt], kf[0], kf[2]);
                mma16816h(s1p, qfh[kt], kf[1], kf[3]);
                mma16816h(s1p, qfl[kt], kf[1], kf[3]);
            }
        };
        // exp2 + fp16 pack + l accumulation
        auto exppack = [&](float* s0p, float* s1p, uint32_t* ph) {
#pragma unroll
            for (int e = 0; e < 4; e++) { s0p[e] = ex2(s0p[e]); s1p[e] = ex2(s1p[e]); }
            l0 += s0p[0] + s0p[1] + s1p[0] + s1p[1];
            l1 += s0p[2] + s0p[3] + s1p[2] + s1p[3];
            ph[0] = pack2h(s0p[0], s0p[1]);
            ph[1] = pack2h(s0p[2], s0p[3]);
            ph[2] = pack2h(s1p[0], s1p[1]);
            ph[3] = pack2h(s1p[2], s1p[3]);
        };
        // PV of block g: o += P_g(fp16) @ Vh  -- 1 MMA per og-half
        auto pv_block = [&](int g, const uint32_t* ph) {
#pragma unroll
            for (int og = 0; og < 4; og++) {
                uint32_t vf[4];
                ldsm_x4_t(vf, Vh + lofs + g * 16 * 144 + og * 32);
                mma16816h(o[2 * og],     ph, vf[0], vf[1]);
                mma16816h(o[2 * og + 1], ph, vf[2], vf[3]);
            }
        };

        float sA0[4], sA1[4], sB0[4], sB1[4];
        uint32_t pA[4], pB[4];

        qk_block(0, sA0, sA1);
        exppack(sA0, sA1, pA);

        qk_block(1, sB0, sB1);
        pv_block(0, pA);
        exppack(sB0, sB1, pB);

        qk_block(2, sA0, sA1);
        pv_block(1, pB);
        exppack(sA0, sA1, pA);

        qk_block(3, sB0, sB1);
        pv_block(2, pA);
        exppack(sB0, sB1, pB);

        pv_block(3, pB);
    }

    // epilogue: reduce l across quad lanes once, normalize, store bf16 splits
    l0 += __shfl_xor_sync(0xffffffffu, l0, 1);
    l0 += __shfl_xor_sync(0xffffffffu, l0, 2);
    l1 += __shfl_xor_sync(0xffffffffu, l1, 1);
    l1 += __shfl_xor_sync(0xffffffffu, l1, 2);
    const float inv0 = 1.f / l0;
    const float inv1 = 1.f / l1;
    const int row0 = q0 + wid * 16 + (lane >> 2);
    const int col0 = h * DH_ + 2 * (lane & 3);
    const size_t p0 = ((size_t)b * S_ + row0) * D_ + col0;
    const size_t p1 = p0 + 8 * D_;
#pragma unroll
    for (int nt = 0; nt < 8; nt++) {
        uint32_t hi, lo;
        split2(o[nt][0] * inv0, o[nt][1] * inv0, hi, lo);
        *reinterpret_cast<uint32_t*>(g_ch + p0 + nt * 8) = hi;
        *reinterpret_cast<uint32_t*>(g_cl + p0 + nt * 8) = lo;
        split2(o[nt][2] * inv1, o[nt][3] * inv1, hi, lo);
        *reinterpret_cast<uint32_t*>(g_ch + p1 + nt * 8) = hi;
        *reinterpret_cast<uint32_t*>(g_cl + p1 + nt * 8) = lo;
    }
}

// ---------------------------------------------------------------------------
// Launch
// ---------------------------------------------------------------------------
extern "C" void kernel_launch(void* const* d_in, const int* in_sizes, int n_in,
                              void* d_out, int out_size)
{
    const float* x  = (const float*)d_in[0];
    const float* Wq = (const float*)d_in[1];
    const float* bq = (const float*)d_in[2];
    const float* Wk = (const float*)d_in[3];
    const float* bk = (const float*)d_in[4];
    const float* Wv = (const float*)d_in[5];
    const float* bv = (const float*)d_in[6];
    const float* Wo = (const float*)d_in[7];
    const float* bo = (const float*)d_in[8];
    const float* ls = (const float*)d_in[9];
    float* out = (float*)d_out;

    xsplit_kernel<<<(M_ * D_) / 1024, 256>>>(x);
    wsplit_kernel<<<4 * (DD_ / 1024), 256>>>(Wq, Wk, Wv, Wo);

    cudaFuncSetAttribute(qkv_gemm, cudaFuncAttributeMaxDynamicSharedMemorySize, GEMM_SMEM);
    cudaFuncSetAttribute(o_gemm,   cudaFuncAttributeMaxDynamicSharedMemorySize, GEMM_SMEM);
    cudaFuncSetAttribute(attn_mma, cudaFuncAttributeMaxDynamicSharedMemorySize, ATTN_SMEM);

    qkv_gemm<<<dim3(18, M_ / 128), 256, GEMM_SMEM>>>(bq, bk, bv, ls);

    attn_mma<<<dim3(S_ / 128, B_ * H_), 256, ATTN_SMEM>>>(ls);

    o_gemm<<<dim3(D_ / 128, M_ / 128), 256, GEMM_SMEM>>>(bo, out);
}

// round 13
// speedup vs baseline: 1.7670x; 1.3175x over previous
#include <cuda_runtime.h>
#include <cuda_bf16.h>
#include <cuda_fp16.h>
#include <math.h>
#include <cstdint>

#define B_  4
#define S_  2048
#define D_  768
#define H_  12
#define DH_ 64
#define M_  (B_*S_)          // 8192
#define NROWS_ (B_*H_*S_)    // 98304
#define QKVN_ (NROWS_*DH_)   // 6291456
#define DD_  (D_*D_)         // 589824
#define LOG2E_ 1.4426950408889634f

// Scratch (allocation-free: static __device__ globals)
__device__ __nv_bfloat16 g_xh[M_*D_],  g_xl[M_*D_];    // x bf16 split (qk GEMMs)
__device__ __half        g_xf[M_*D_];                  // x fp16 (v GEMM)
__device__ __nv_bfloat16 g_wh[2*DD_],  g_wl[2*DD_];    // Wq,Wk bf16 split
__device__ __half        g_wvf[DD_],   g_wof[DD_];     // Wv,Wo fp16
__device__ __half        g_qh[QKVN_];                  // q fp16 (prescaled, normalized)
__device__ __half        g_kh[QKVN_];                  // k fp16 (normalized)
__device__ __half        g_vh[QKVN_];                  // v fp16
__device__ __half        g_cf[M_*D_];                  // ctx fp16

// ===========================================================================
// Helpers
// ===========================================================================
__device__ __forceinline__ uint32_t smem_u32(const void* p) {
    uint32_t r;
    asm("{ .reg .u64 t; cvta.to.shared.u64 t, %1; cvt.u32.u64 %0, t; }"
        : "=r"(r) : "l"(p));
    return r;
}
__device__ __forceinline__ void ldsm_x4(uint32_t* r, uint32_t addr) {
    asm volatile("ldmatrix.sync.aligned.m8n8.x4.shared.b16 {%0,%1,%2,%3}, [%4];"
                 : "=r"(r[0]), "=r"(r[1]), "=r"(r[2]), "=r"(r[3]) : "r"(addr));
}
__device__ __forceinline__ void ldsm_x4_t(uint32_t* r, uint32_t addr) {
    asm volatile("ldmatrix.sync.aligned.m8n8.x4.trans.shared.b16 {%0,%1,%2,%3}, [%4];"
                 : "=r"(r[0]), "=r"(r[1]), "=r"(r[2]), "=r"(r[3]) : "r"(addr));
}
// bf16 in, fp32 accum
__device__ __forceinline__ void mma16816(float* d, const uint32_t* a,
                                         uint32_t b0, uint32_t b1) {
    asm volatile(
        "mma.sync.aligned.m16n8k16.row.col.f32.bf16.bf16.f32 "
        "{%0,%1,%2,%3}, {%4,%5,%6,%7}, {%8,%9}, {%0,%1,%2,%3};"
        : "+f"(d[0]), "+f"(d[1]), "+f"(d[2]), "+f"(d[3])
        : "r"(a[0]), "r"(a[1]), "r"(a[2]), "r"(a[3]), "r"(b0), "r"(b1));
}
// fp16 in, fp32 accum
__device__ __forceinline__ void mma16816h(float* d, const uint32_t* a,
                                          uint32_t b0, uint32_t b1) {
    asm volatile(
        "mma.sync.aligned.m16n8k16.row.col.f32.f16.f16.f32 "
        "{%0,%1,%2,%3}, {%4,%5,%6,%7}, {%8,%9}, {%0,%1,%2,%3};"
        : "+f"(d[0]), "+f"(d[1]), "+f"(d[2]), "+f"(d[3])
        : "r"(a[0]), "r"(a[1]), "r"(a[2]), "r"(a[3]), "r"(b0), "r"(b1));
}
// round-to-nearest bf16 hi/lo split
__device__ __forceinline__ void split2(float x0, float x1, uint32_t& hi, uint32_t& lo) {
    __nv_bfloat16 h0 = __float2bfloat16_rn(x0);
    __nv_bfloat16 h1 = __float2bfloat16_rn(x1);
    __nv_bfloat16 l0 = __float2bfloat16_rn(x0 - __bfloat162float(h0));
    __nv_bfloat16 l1 = __float2bfloat16_rn(x1 - __bfloat162float(h1));
    hi = (uint32_t)__bfloat16_as_ushort(h0) | ((uint32_t)__bfloat16_as_ushort(h1) << 16);
    lo = (uint32_t)__bfloat16_as_ushort(l0) | ((uint32_t)__bfloat16_as_ushort(l1) << 16);
}
// pack two fp32 -> fp16x2 (rn), element0 in low half
__device__ __forceinline__ uint32_t pack2h(float x0, float x1) {
    uint32_t d;
    asm("cvt.rn.f16x2.f32 %0, %1, %2;" : "=r"(d) : "f"(x1), "f"(x0));
    return d;
}
__device__ __forceinline__ float ex2(float x) {
    float y;
    asm("ex2.approx.f32 %0, %1;" : "=f"(y) : "f"(x));
    return y;
}
__device__ __forceinline__ void cp16(uint32_t dst, const void* src) {
    asm volatile("cp.async.cg.shared.global [%0], [%1], 16;" :: "r"(dst), "l"(src));
}
#define CP_COMMIT() asm volatile("cp.async.commit_group;" ::: "memory")
#define CP_WAIT(n)  asm volatile("cp.async.wait_group %0;" :: "n"(n) : "memory")

// ===========================================================================
// split kernels
// ===========================================================================
__global__ void __launch_bounds__(256)
xsplit_kernel(const float* __restrict__ src)
{
    const int i = (blockIdx.x * 256 + threadIdx.x) * 4;
    float4 v = *reinterpret_cast<const float4*>(src + i);
    uint32_t h0, l0, h1, l1;
    split2(v.x, v.y, h0, l0);
    split2(v.z, v.w, h1, l1);
    *reinterpret_cast<uint2*>(g_xh + i) = make_uint2(h0, h1);
    *reinterpret_cast<uint2*>(g_xl + i) = make_uint2(l0, l1);
    *reinterpret_cast<uint2*>(g_xf + i) =
        make_uint2(pack2h(v.x, v.y), pack2h(v.z, v.w));
}
__global__ void __launch_bounds__(256)
wsplit_kernel(const float* __restrict__ Wq, const float* __restrict__ Wk,
              const float* __restrict__ Wv, const float* __restrict__ Wo)
{
    const int per = DD_ / 1024;                   // 576
    const int wsel = blockIdx.x / per;
    const int bx   = blockIdx.x % per;
    const float* src = (wsel == 0) ? Wq : (wsel == 1) ? Wk : (wsel == 2) ? Wv : Wo;
    const int i = (bx * 256 + threadIdx.x) * 4;
    float4 v = *reinterpret_cast<const float4*>(src + i);
    if (wsel < 2) {
        uint32_t h0, l0, h1, l1;
        split2(v.x, v.y, h0, l0);
        split2(v.z, v.w, h1, l1);
        const size_t o = (size_t)wsel * DD_ + i;
        *reinterpret_cast<uint2*>(g_wh + o) = make_uint2(h0, h1);
        *reinterpret_cast<uint2*>(g_wl + o) = make_uint2(l0, l1);
    } else {
        __half* dst = (wsel == 2) ? g_wvf : g_wof;
        *reinterpret_cast<uint2*>(dst + i) =
            make_uint2(pack2h(v.x, v.y), pack2h(v.z, v.w));
    }
}

// ===========================================================================
// bf16x3 GEMM mainloop: acc = A @ W^T, 128x128 tile (q,k projections)
// ===========================================================================
#define LDK_  40
#define GARR  10240
#define GEMM_SMEM (8 * GARR)        // 80KB

__device__ __forceinline__ void gemm_body(
    const __nv_bfloat16* __restrict__ Ah, const __nv_bfloat16* __restrict__ Al,
    const __nv_bfloat16* __restrict__ Wh, const __nv_bfloat16* __restrict__ Wl,
    int m0, int n0, char* smem, float acc[4][4][4])
{
    const int tid    = threadIdx.x;
    const int lane   = tid & 31;
    const int wid    = tid >> 5;
    const int warp_m = wid & 1;
    const int warp_n = wid >> 1;
    const uint32_t sb = smem_u32(smem);

#pragma unroll
    for (int i = 0; i < 4; i++)
#pragma unroll
        for (int j = 0; j < 4; j++)
#pragma unroll
            for (int e = 0; e < 4; e++) acc[i][j][e] = 0.f;

    const int grow = tid >> 1;
    const int c16  = (tid & 1) * 2;
    const __nv_bfloat16* s0 = Ah + (size_t)(m0 + grow) * D_;
    const __nv_bfloat16* s1 = Al + (size_t)(m0 + grow) * D_;
    const __nv_bfloat16* s2 = Wh + (size_t)(n0 + grow) * D_;
    const __nv_bfloat16* s3 = Wl + (size_t)(n0 + grow) * D_;

    auto issue = [&](int kc, int bsel) {
        const uint32_t dst = sb + bsel * 4 * GARR + grow * 80 + c16 * 16;
#pragma unroll
        for (int j = 0; j < 2; j++) {
            cp16(dst + j * 16,            s0 + kc + (c16 + j) * 8);
            cp16(dst + j * 16 + GARR,     s1 + kc + (c16 + j) * 8);
            cp16(dst + j * 16 + 2 * GARR, s2 + kc + (c16 + j) * 8);
            cp16(dst + j * 16 + 3 * GARR, s3 + kc + (c16 + j) * 8);
        }
    };

    const int r_a = lane & 15, c_a = (lane >> 4) * 8;
    const int r_b = (lane & 7) | ((lane >> 4) << 3);
    const int c_b = ((lane >> 3) & 1) * 8;
    const uint32_t offA = ((warp_m * 64 + r_a) * LDK_ + c_a) * 2;
    const uint32_t offB = ((warp_n * 32 + r_b) * LDK_ + c_b) * 2;

    issue(0, 0);
    CP_COMMIT();

    const int NK = D_ / 32;   // 24
    for (int it = 0; it < NK; it++) {
        if (it + 1 < NK) {
            issue((it + 1) * 32, (it + 1) & 1);
            CP_COMMIT();
            CP_WAIT(1);
        } else {
            CP_WAIT(0);
        }
        __syncthreads();

        const uint32_t bAh = sb + ((it & 1) * 4 + 0) * GARR;
        const uint32_t bAl = bAh + GARR;
        const uint32_t bWh = bAh + 2 * GARR;
        const uint32_t bWl = bAh + 3 * GARR;

#pragma unroll
        for (int ks = 0; ks < 2; ks++) {
            const uint32_t ko = ks * 32;
            uint32_t ah[4][4], al[4][4];
#pragma unroll
            for (int mt = 0; mt < 4; mt++) {
                ldsm_x4(ah[mt], bAh + offA + ko + mt * 16 * LDK_ * 2);
                ldsm_x4(al[mt], bAl + offA + ko + mt * 16 * LDK_ * 2);
            }
            uint32_t bh[8], bl[8];
#pragma unroll
            for (int g = 0; g < 2; g++) {
                ldsm_x4(&bh[g * 4], bWh + offB + ko + g * 16 * LDK_ * 2);
                ldsm_x4(&bl[g * 4], bWl + offB + ko + g * 16 * LDK_ * 2);
            }
#pragma unroll
            for (int mt = 0; mt < 4; mt++)
#pragma unroll
                for (int nt = 0; nt < 4; nt++) {
                    mma16816(acc[mt][nt], ah[mt], bh[nt * 2], bh[nt * 2 + 1]);
                    mma16816(acc[mt][nt], ah[mt], bl[nt * 2], bl[nt * 2 + 1]);
                    mma16816(acc[mt][nt], al[mt], bh[nt * 2], bh[nt * 2 + 1]);
                }
        }
        __syncthreads();
    }
}

// ===========================================================================
// fp16 1-combo GEMM mainloop: acc = A @ W^T, 128x128 tile (v, o projections)
// ===========================================================================
#define GEMMH_SMEM (4 * GARR)       // 40KB: 2 buffers x {A, W}

__device__ __forceinline__ void gemm_fp16_body(
    const __half* __restrict__ A, const __half* __restrict__ W,
    int m0, int n0, char* smem, float acc[4][4][4])
{
    const int tid    = threadIdx.x;
    const int lane   = tid & 31;
    const int wid    = tid >> 5;
    const int warp_m = wid & 1;
    const int warp_n = wid >> 1;
    const uint32_t sb = smem_u32(smem);

#pragma unroll
    for (int i = 0; i < 4; i++)
#pragma unroll
        for (int j = 0; j < 4; j++)
#pragma unroll
            for (int e = 0; e < 4; e++) acc[i][j][e] = 0.f;

    const int grow = tid >> 1;
    const int c16  = (tid & 1) * 2;
    const __half* s0 = A + (size_t)(m0 + grow) * D_;
    const __half* s1 = W + (size_t)(n0 + grow) * D_;

    auto issue = [&](int kc, int bsel) {
        const uint32_t dst = sb + bsel * 2 * GARR + grow * 80 + c16 * 16;
#pragma unroll
        for (int j = 0; j < 2; j++) {
            cp16(dst + j * 16,        s0 + kc + (c16 + j) * 8);
            cp16(dst + j * 16 + GARR, s1 + kc + (c16 + j) * 8);
        }
    };

    const int r_a = lane & 15, c_a = (lane >> 4) * 8;
    const int r_b = (lane & 7) | ((lane >> 4) << 3);
    const int c_b = ((lane >> 3) & 1) * 8;
    const uint32_t offA = ((warp_m * 64 + r_a) * LDK_ + c_a) * 2;
    const uint32_t offB = ((warp_n * 32 + r_b) * LDK_ + c_b) * 2;

    issue(0, 0);
    CP_COMMIT();

    const int NK = D_ / 32;   // 24
    for (int it = 0; it < NK; it++) {
        if (it + 1 < NK) {
            issue((it + 1) * 32, (it + 1) & 1);
            CP_COMMIT();
            CP_WAIT(1);
        } else {
            CP_WAIT(0);
        }
        __syncthreads();

        const uint32_t bA = sb + ((it & 1) * 2) * GARR;
        const uint32_t bW = bA + GARR;

#pragma unroll
        for (int ks = 0; ks < 2; ks++) {
            const uint32_t ko = ks * 32;
            uint32_t ah[4][4];
#pragma unroll
            for (int mt = 0; mt < 4; mt++)
                ldsm_x4(ah[mt], bA + offA + ko + mt * 16 * LDK_ * 2);
            uint32_t bh[8];
#pragma unroll
            for (int g = 0; g < 2; g++)
                ldsm_x4(&bh[g * 4], bW + offB + ko + g * 16 * LDK_ * 2);
#pragma unroll
            for (int mt = 0; mt < 4; mt++)
#pragma unroll
                for (int nt = 0; nt < 4; nt++)
                    mma16816h(acc[mt][nt], ah[mt], bh[nt * 2], bh[nt * 2 + 1]);
        }
        __syncthreads();
    }
}

// ===========================================================================
// fused QK GEMM (bf16x3): proj + bias + L2 norm + scale(q) -> fp16 store.
// grid.x = 12 (wsel = x/6: 0=q, 1=k).
// ===========================================================================
__global__ void __launch_bounds__(256, 2)
qk_gemm(const float* __restrict__ bq, const float* __restrict__ bk,
        const float* __restrict__ ls)
{
    extern __shared__ char smem[];
    const int wsel = blockIdx.x / 6;
    const int n0   = (blockIdx.x % 6) * 128;
    const int m0   = blockIdx.y * 128;

    float acc[4][4][4];
    gemm_body(g_xh, g_xl, g_wh + (size_t)wsel * DD_, g_wl + (size_t)wsel * DD_,
              m0, n0, smem, acc);

    const int tid  = threadIdx.x;
    const int lane = tid & 31;
    const int wid  = tid >> 5;
    const int warp_m = wid & 1, warp_n = wid >> 1;

    const float* bias = (wsel == 0) ? bq : bk;
    __half* dst = (wsel == 0) ? g_qh : g_kh;

    float2 bv2[4];
#pragma unroll
    for (int nt = 0; nt < 4; nt++)
        bv2[nt] = *reinterpret_cast<const float2*>(
            &bias[n0 + warp_n * 32 + nt * 8 + 2 * (lane & 3)]);
#pragma unroll
    for (int mt = 0; mt < 4; mt++)
#pragma unroll
        for (int nt = 0; nt < 4; nt++) {
            acc[mt][nt][0] += bv2[nt].x; acc[mt][nt][1] += bv2[nt].y;
            acc[mt][nt][2] += bv2[nt].x; acc[mt][nt][3] += bv2[nt].y;
        }

    __syncthreads();
    float* sq = reinterpret_cast<float*>(smem);   // [128][4]

#pragma unroll
    for (int mt = 0; mt < 4; mt++)
#pragma unroll
        for (int half = 0; half < 2; half++) {
            const int r = warp_m * 64 + mt * 16 + (lane >> 2) + half * 8;
            float p = 0.f;
#pragma unroll
            for (int nt = 0; nt < 4; nt++) {
                const float a = acc[mt][nt][half * 2], bvv = acc[mt][nt][half * 2 + 1];
                p += a * a + bvv * bvv;
            }
            p += __shfl_xor_sync(0xffffffffu, p, 1);
            p += __shfl_xor_sync(0xffffffffu, p, 2);
            if ((lane & 3) == 0) sq[r * 4 + warp_n] = p;
        }
    __syncthreads();

    float scl = 1.f;
    if (wsel == 0) {
        const int hh = 2 * (blockIdx.x % 6) + (warp_n >> 1);
        scl = __expf(fminf(ls[hh], 4.6051701859880914f)) * LOG2E_;
    }

#pragma unroll
    for (int mt = 0; mt < 4; mt++) {
#pragma unroll
        for (int half = 0; half < 2; half++) {
            const int r = warp_m * 64 + mt * 16 + (lane >> 2) + half * 8;
            const float s2 = sq[r * 4 + (warp_n & 2)] + sq[r * 4 + (warp_n & 2) + 1];
            const float inv = scl / fmaxf(sqrtf(s2), 1e-12f);
            const int m  = m0 + r;
            const int bb = m >> 11, ss = m & (S_ - 1);
#pragma unroll
            for (int nt = 0; nt < 4; nt++) {
                const int n  = n0 + warp_n * 32 + nt * 8 + 2 * (lane & 3);
                const int hh = n >> 6, dd = n & 63;
                const size_t idx = (((size_t)(bb * H_ + hh)) * S_ + ss) * DH_ + dd;
                *reinterpret_cast<uint32_t*>(&dst[idx]) =
                    pack2h(acc[mt][nt][half * 2] * inv, acc[mt][nt][half * 2 + 1] * inv);
            }
        }
    }
}

// v projection (fp16 1-combo): x_f @ Wv^T + bv -> head-split fp16 g_vh
__global__ void __launch_bounds__(256, 2)
v_gemm(const float* __restrict__ bv)
{
    extern __shared__ char smem[];
    const int n0 = blockIdx.x * 128;
    const int m0 = blockIdx.y * 128;

    float acc[4][4][4];
    gemm_fp16_body(g_xf, g_wvf, m0, n0, smem, acc);

    const int lane = threadIdx.x & 31;
    const int wid  = threadIdx.x >> 5;
    const int warp_m = wid & 1, warp_n = wid >> 1;
#pragma unroll
    for (int mt = 0; mt < 4; mt++) {
#pragma unroll
        for (int nt = 0; nt < 4; nt++) {
            const int n = n0 + warp_n * 32 + nt * 8 + 2 * (lane & 3);
            const float2 bv2 = *reinterpret_cast<const float2*>(&bv[n]);
            const int hh = n >> 6, dd = n & 63;
#pragma unroll
            for (int half = 0; half < 2; half++) {
                const int m = m0 + warp_m * 64 + mt * 16 + (lane >> 2) + half * 8;
                const int bb = m >> 11, ss = m & (S_ - 1);
                const size_t idx = (((size_t)(bb * H_ + hh)) * S_ + ss) * DH_ + dd;
                *reinterpret_cast<uint32_t*>(&g_vh[idx]) =
                    pack2h(acc[mt][nt][half * 2] + bv2.x,
                           acc[mt][nt][half * 2 + 1] + bv2.y);
            }
        }
    }
}

// output projection (fp16 1-combo): ctx_f @ Wo^T + bo -> fp32 out
__global__ void __launch_bounds__(256, 2)
o_gemm(const float* __restrict__ bo, float* __restrict__ out)
{
    extern __shared__ char smem[];
    const int n0 = blockIdx.x * 128;
    const int m0 = blockIdx.y * 128;

    float acc[4][4][4];
    gemm_fp16_body(g_cf, g_wof, m0, n0, smem, acc);

    const int lane = threadIdx.x & 31;
    const int wid  = threadIdx.x >> 5;
    const int warp_m = wid & 1, warp_n = wid >> 1;
#pragma unroll
    for (int mt = 0; mt < 4; mt++) {
#pragma unroll
        for (int nt = 0; nt < 4; nt++) {
            const int n = n0 + warp_n * 32 + nt * 8 + 2 * (lane & 3);
            const float2 bv2 = *reinterpret_cast<const float2*>(&bo[n]);
#pragma unroll
            for (int half = 0; half < 2; half++) {
                const int m = m0 + warp_m * 64 + mt * 16 + (lane >> 2) + half * 8;
                float2 o;
                o.x = acc[mt][nt][half * 2 + 0] + bv2.x;
                o.y = acc[mt][nt][half * 2 + 1] + bv2.y;
                *reinterpret_cast<float2*>(out + (size_t)m * D_ + n) = o;
            }
        }
    }
}

// ===========================================================================
// HMMA flash attention, fixed-max softmax, all single-fp16 tensor path.
// QK: q(fp16) x k(fp16) -- 1 MMA/kt-half. PV: P(fp16) x v(fp16) -- 1 MMA.
// 16 MMAs per 16-key block (was 24).
// ===========================================================================
#define ABUF   9216
#define ATTN_SMEM (6 * ABUF)       // 3 stages x {Kh, Vh}

__global__ void __launch_bounds__(256, 2)
attn_mma(const float* __restrict__ ls)
{
    extern __shared__ char sm[];
    const uint32_t sbase = smem_u32(sm);
    const int tid  = threadIdx.x;
    const int lane = tid & 31;
    const int wid  = tid >> 5;
    const int bh   = blockIdx.y;
    const int h    = bh % H_;
    const int b    = bh / H_;
    const int q0   = blockIdx.x * 128;
    const size_t base = (size_t)bh * S_ * DH_;
    const float Mfix = __expf(fminf(ls[h], 4.6051701859880914f)) * LOG2E_;

    // stage Q (fp16, 128x64) into smem, build A-fragments, release
    {
        const __half* gq = g_qh + base + (size_t)q0 * DH_;
#pragma unroll
        for (int i = 0; i < 4; i++) {
            const int idx = (i << 8) + tid;        // 0..1023
            const int row = idx >> 3, c = idx & 7;
            const uint4 v = *reinterpret_cast<const uint4*>(gq + row * DH_ + c * 8);
            *reinterpret_cast<uint4*>(sm + row * 144 + c * 16) = v;
        }
    }
    __syncthreads();
    uint32_t qf[4][4];
    {
        const uint32_t qa = sbase + (wid * 16 + (lane & 15)) * 144 + (lane >> 4) * 16;
#pragma unroll
        for (int kt = 0; kt < 4; kt++)
            ldsm_x4(qf[kt], qa + kt * 32);
    }
    __syncthreads();

    float o[8][4];
#pragma unroll
    for (int nt = 0; nt < 8; nt++)
#pragma unroll
        for (int e = 0; e < 4; e++) o[nt][e] = 0.f;
    float l0 = 0.f, l1 = 0.f;

    const uint32_t lofs = (lane & 15) * 144 + (lane >> 4) * 16;

    const __half* gkh = g_kh + base;
    const __half* gvh = g_vh + base;

    auto issue = [&](int it, int bsel) {
        const int koff = it * 64 * DH_;
#pragma unroll
        for (int i = 0; i < 4; i++) {
            const int idx = (i << 8) + tid;        // 0..1023
            const int arr = idx >> 9;              // 0..1
            const int row = (idx >> 3) & 63;
            const int c   = idx & 7;
            const __half* gp = (arr == 0 ? gkh : gvh) + koff + row * DH_ + c * 8;
            cp16(sbase + (bsel * 2 + arr) * ABUF + row * 144 + c * 16, gp);
        }
    };

    issue(0, 0); CP_COMMIT();
    issue(1, 1); CP_COMMIT();

    const int NIT = S_ / 64;   // 32
    for (int it = 0; it < NIT; it++) {
        if (it + 1 < NIT) { CP_WAIT(1); } else { CP_WAIT(0); }
        __syncthreads();
        if (it + 2 < NIT) { issue(it + 2, (it + 2) % 3); CP_COMMIT(); }

        const uint32_t Kh = sbase + ((it % 3) * 2) * ABUF;
        const uint32_t Vh = Kh + ABUF;

        auto qk_block = [&](int g, float* s0p, float* s1p) {
#pragma unroll
            for (int e = 0; e < 4; e++) { s0p[e] = -Mfix; s1p[e] = -Mfix; }
#pragma unroll
            for (int kt = 0; kt < 4; kt++) {
                uint32_t kf[4];
                ldsm_x4(kf, Kh + lofs + g * 16 * 144 + kt * 32);
                mma16816h(s0p, qf[kt], kf[0], kf[2]);
                mma16816h(s1p, qf[kt], kf[1], kf[3]);
            }
        };
        auto exppack = [&](float* s0p, float* s1p, uint32_t* ph) {
#pragma unroll
            for (int e = 0; e < 4; e++) { s0p[e] = ex2(s0p[e]); s1p[e] = ex2(s1p[e]); }
            l0 += s0p[0] + s0p[1] + s1p[0] + s1p[1];
            l1 += s0p[2] + s0p[3] + s1p[2] + s1p[3];
            ph[0] = pack2h(s0p[0], s0p[1]);
            ph[1] = pack2h(s0p[2], s0p[3]);
            ph[2] = pack2h(s1p[0], s1p[1]);
            ph[3] = pack2h(s1p[2], s1p[3]);
        };
        auto pv_block = [&](int g, const uint32_t* ph) {
#pragma unroll
            for (int og = 0; og < 4; og++) {
                uint32_t vf[4];
                ldsm_x4_t(vf, Vh + lofs + g * 16 * 144 + og * 32);
                mma16816h(o[2 * og],     ph, vf[0], vf[1]);
                mma16816h(o[2 * og + 1], ph, vf[2], vf[3]);
            }
        };

        float sA0[4], sA1[4], sB0[4], sB1[4];
        uint32_t pA[4], pB[4];

        qk_block(0, sA0, sA1);
        exppack(sA0, sA1, pA);

        qk_block(1, sB0, sB1);
        pv_block(0, pA);
        exppack(sB0, sB1, pB);

        qk_block(2, sA0, sA1);
        pv_block(1, pB);
        exppack(sA0, sA1, pA);

        qk_block(3, sB0, sB1);
        pv_block(2, pA);
        exppack(sB0, sB1, pB);

        pv_block(3, pB);
    }

    // epilogue: quad-reduce l, normalize, store ctx as single fp16
    l0 += __shfl_xor_sync(0xffffffffu, l0, 1);
    l0 += __shfl_xor_sync(0xffffffffu, l0, 2);
    l1 += __shfl_xor_sync(0xffffffffu, l1, 1);
    l1 += __shfl_xor_sync(0xffffffffu, l1, 2);
    const float inv0 = 1.f / l0;
    const float inv1 = 1.f / l1;
    const int row0 = q0 + wid * 16 + (lane >> 2);
    const int col0 = h * DH_ + 2 * (lane & 3);
    const size_t p0 = ((size_t)b * S_ + row0) * D_ + col0;
    const size_t p1 = p0 + 8 * D_;
#pragma unroll
    for (int nt = 0; nt < 8; nt++) {
        *reinterpret_cast<uint32_t*>(g_cf + p0 + nt * 8) =
            pack2h(o[nt][0] * inv0, o[nt][1] * inv0);
        *reinterpret_cast<uint32_t*>(g_cf + p1 + nt * 8) =
            pack2h(o[nt][2] * inv1, o[nt][3] * inv1);
    }
}

// ---------------------------------------------------------------------------
// Launch
// ---------------------------------------------------------------------------
extern "C" void kernel_launch(void* const* d_in, const int* in_sizes, int n_in,
                              void* d_out, int out_size)
{
    const float* x  = (const float*)d_in[0];
    const float* Wq = (const float*)d_in[1];
    const float* bq = (const float*)d_in[2];
    const float* Wk = (const float*)d_in[3];
    const float* bk = (const float*)d_in[4];
    const float* Wv = (const float*)d_in[5];
    const float* bv = (const float*)d_in[6];
    const float* Wo = (const float*)d_in[7];
    const float* bo = (const float*)d_in[8];
    const float* ls = (const float*)d_in[9];
    float* out = (float*)d_out;

    xsplit_kernel<<<(M_ * D_) / 1024, 256>>>(x);
    wsplit_kernel<<<4 * (DD_ / 1024), 256>>>(Wq, Wk, Wv, Wo);

    cudaFuncSetAttribute(qk_gemm, cudaFuncAttributeMaxDynamicSharedMemorySize, GEMM_SMEM);
    cudaFuncSetAttribute(v_gemm,  cudaFuncAttributeMaxDynamicSharedMemorySize, GEMMH_SMEM);
    cudaFuncSetAttribute(o_gemm,  cudaFuncAttributeMaxDynamicSharedMemorySize, GEMMH_SMEM);
    cudaFuncSetAttribute(attn_mma, cudaFuncAttributeMaxDynamicSharedMemorySize, ATTN_SMEM);

    qk_gemm<<<dim3(12, M_ / 128), 256, GEMM_SMEM>>>(bq, bk, ls);
    v_gemm<<<dim3(6, M_ / 128), 256, GEMMH_SMEM>>>(bv);

    attn_mma<<<dim3(S_ / 128, B_ * H_), 256, ATTN_SMEM>>>(ls);

    o_gemm<<<dim3(6, M_ / 128), 256, GEMMH_SMEM>>>(bo, out);
}

// round 14
// speedup vs baseline: 2.0993x; 1.1881x over previous
#include <cuda_runtime.h>
#include <cuda_bf16.h>
#include <cuda_fp16.h>
#include <math.h>
#include <cstdint>

#define B_  4
#define S_  2048
#define D_  768
#define H_  12
#define DH_ 64
#define M_  (B_*S_)          // 8192
#define NROWS_ (B_*H_*S_)    // 98304
#define QKVN_ (NROWS_*DH_)   // 6291456
#define DD_  (D_*D_)         // 589824
#define LOG2E_ 1.4426950408889634f

// Scratch (allocation-free: static __device__ globals)
__device__ __half g_xf[M_*D_];                     // x fp16
__device__ __half g_wh[2*DD_], g_wl[2*DD_];        // Wq,Wk fp16 split
__device__ __half g_wvf[DD_],  g_wof[DD_];         // Wv,Wo fp16
__device__ __half g_qh[QKVN_];                     // q fp16 (prescaled, normalized)
__device__ __half g_kh[QKVN_];                     // k fp16 (normalized)
__device__ __half g_vh[QKVN_];                     // v fp16
__device__ __half g_cf[M_*D_];                     // ctx fp16

// ===========================================================================
// Helpers
// ===========================================================================
__device__ __forceinline__ uint32_t smem_u32(const void* p) {
    uint32_t r;
    asm("{ .reg .u64 t; cvta.to.shared.u64 t, %1; cvt.u32.u64 %0, t; }"
        : "=r"(r) : "l"(p));
    return r;
}
__device__ __forceinline__ void ldsm_x4(uint32_t* r, uint32_t addr) {
    asm volatile("ldmatrix.sync.aligned.m8n8.x4.shared.b16 {%0,%1,%2,%3}, [%4];"
                 : "=r"(r[0]), "=r"(r[1]), "=r"(r[2]), "=r"(r[3]) : "r"(addr));
}
__device__ __forceinline__ void ldsm_x4_t(uint32_t* r, uint32_t addr) {
    asm volatile("ldmatrix.sync.aligned.m8n8.x4.trans.shared.b16 {%0,%1,%2,%3}, [%4];"
                 : "=r"(r[0]), "=r"(r[1]), "=r"(r[2]), "=r"(r[3]) : "r"(addr));
}
// fp16 in, fp32 accum
__device__ __forceinline__ void mma16816h(float* d, const uint32_t* a,
                                          uint32_t b0, uint32_t b1) {
    asm volatile(
        "mma.sync.aligned.m16n8k16.row.col.f32.f16.f16.f32 "
        "{%0,%1,%2,%3}, {%4,%5,%6,%7}, {%8,%9}, {%0,%1,%2,%3};"
        : "+f"(d[0]), "+f"(d[1]), "+f"(d[2]), "+f"(d[3])
        : "r"(a[0]), "r"(a[1]), "r"(a[2]), "r"(a[3]), "r"(b0), "r"(b1));
}
// fp16 hi/lo split
__device__ __forceinline__ void split2h(float x0, float x1, uint32_t& hi, uint32_t& lo) {
    __half h0 = __float2half_rn(x0);
    __half h1 = __float2half_rn(x1);
    __half l0 = __float2half_rn(x0 - __half2float(h0));
    __half l1 = __float2half_rn(x1 - __half2float(h1));
    hi = (uint32_t)__half_as_ushort(h0) | ((uint32_t)__half_as_ushort(h1) << 16);
    lo = (uint32_t)__half_as_ushort(l0) | ((uint32_t)__half_as_ushort(l1) << 16);
}
// pack two fp32 -> fp16x2 (rn), element0 in low half
__device__ __forceinline__ uint32_t pack2h(float x0, float x1) {
    uint32_t d;
    asm("cvt.rn.f16x2.f32 %0, %1, %2;" : "=r"(d) : "f"(x1), "f"(x0));
    return d;
}
__device__ __forceinline__ float ex2(float x) {
    float y;
    asm("ex2.approx.f32 %0, %1;" : "=f"(y) : "f"(x));
    return y;
}
__device__ __forceinline__ void cp16(uint32_t dst, const void* src) {
    asm volatile("cp.async.cg.shared.global [%0], [%1], 16;" :: "r"(dst), "l"(src));
}
#define CP_COMMIT() asm volatile("cp.async.commit_group;" ::: "memory")
#define CP_WAIT(n)  asm volatile("cp.async.wait_group %0;" :: "n"(n) : "memory")

// ===========================================================================
// conversion kernels
// ===========================================================================
__global__ void __launch_bounds__(256)
xconv_kernel(const float* __restrict__ src)
{
    const int i = (blockIdx.x * 256 + threadIdx.x) * 4;
    float4 v = *reinterpret_cast<const float4*>(src + i);
    *reinterpret_cast<uint2*>(g_xf + i) =
        make_uint2(pack2h(v.x, v.y), pack2h(v.z, v.w));
}
__global__ void __launch_bounds__(256)
wsplit_kernel(const float* __restrict__ Wq, const float* __restrict__ Wk,
              const float* __restrict__ Wv, const float* __restrict__ Wo)
{
    const int per = DD_ / 1024;                   // 576
    const int wsel = blockIdx.x / per;
    const int bx   = blockIdx.x % per;
    const float* src = (wsel == 0) ? Wq : (wsel == 1) ? Wk : (wsel == 2) ? Wv : Wo;
    const int i = (bx * 256 + threadIdx.x) * 4;
    float4 v = *reinterpret_cast<const float4*>(src + i);
    if (wsel < 2) {
        uint32_t h0, l0, h1, l1;
        split2h(v.x, v.y, h0, l0);
        split2h(v.z, v.w, h1, l1);
        const size_t o = (size_t)wsel * DD_ + i;
        *reinterpret_cast<uint2*>(g_wh + o) = make_uint2(h0, h1);
        *reinterpret_cast<uint2*>(g_wl + o) = make_uint2(l0, l1);
    } else {
        __half* dst = (wsel == 2) ? g_wvf : g_wof;
        *reinterpret_cast<uint2*>(dst + i) =
            make_uint2(pack2h(v.x, v.y), pack2h(v.z, v.w));
    }
}

// ===========================================================================
// fp16 2-combo GEMM mainloop: acc = A @ (Wh+Wl)^T  (q,k projections)
// 3-stage cp.async ring, one __syncthreads per K-iter.
// ===========================================================================
#define LDK_  40
#define GARR  10240
#define GEMM2_SMEM (9 * GARR)       // 3 stages x {A, Wh, Wl} = 90KB

__device__ __forceinline__ void gemm2_body(
    const __half* __restrict__ A,
    const __half* __restrict__ Wh, const __half* __restrict__ Wl,
    int m0, int n0, char* smem, float acc[4][4][4])
{
    const int tid    = threadIdx.x;
    const int lane   = tid & 31;
    const int wid    = tid >> 5;
    const int warp_m = wid & 1;
    const int warp_n = wid >> 1;
    const uint32_t sb = smem_u32(smem);

#pragma unroll
    for (int i = 0; i < 4; i++)
#pragma unroll
        for (int j = 0; j < 4; j++)
#pragma unroll
            for (int e = 0; e < 4; e++) acc[i][j][e] = 0.f;

    const int grow = tid >> 1;
    const int c16  = (tid & 1) * 2;
    const __half* s0 = A  + (size_t)(m0 + grow) * D_;
    const __half* s1 = Wh + (size_t)(n0 + grow) * D_;
    const __half* s2 = Wl + (size_t)(n0 + grow) * D_;

    auto issue = [&](int kc, int bsel) {
        const uint32_t dst = sb + bsel * 3 * GARR + grow * 80 + c16 * 16;
#pragma unroll
        for (int j = 0; j < 2; j++) {
            cp16(dst + j * 16,            s0 + kc + (c16 + j) * 8);
            cp16(dst + j * 16 + GARR,     s1 + kc + (c16 + j) * 8);
            cp16(dst + j * 16 + 2 * GARR, s2 + kc + (c16 + j) * 8);
        }
    };

    const int r_a = lane & 15, c_a = (lane >> 4) * 8;
    const int r_b = (lane & 7) | ((lane >> 4) << 3);
    const int c_b = ((lane >> 3) & 1) * 8;
    const uint32_t offA = ((warp_m * 64 + r_a) * LDK_ + c_a) * 2;
    const uint32_t offB = ((warp_n * 32 + r_b) * LDK_ + c_b) * 2;

    issue(0, 0);  CP_COMMIT();
    issue(32, 1); CP_COMMIT();

    const int NK = D_ / 32;   // 24
    for (int it = 0; it < NK; it++) {
        if (it + 1 < NK) { CP_WAIT(1); } else { CP_WAIT(0); }
        __syncthreads();
        if (it + 2 < NK) { issue((it + 2) * 32, (it + 2) % 3); CP_COMMIT(); }

        const uint32_t bA  = sb + ((it % 3) * 3) * GARR;
        const uint32_t bWh = bA + GARR;
        const uint32_t bWl = bA + 2 * GARR;

#pragma unroll
        for (int ks = 0; ks < 2; ks++) {
            const uint32_t ko = ks * 32;
            uint32_t ah[4][4];
#pragma unroll
            for (int mt = 0; mt < 4; mt++)
                ldsm_x4(ah[mt], bA + offA + ko + mt * 16 * LDK_ * 2);
            uint32_t bh[8], bl[8];
#pragma unroll
            for (int g = 0; g < 2; g++) {
                ldsm_x4(&bh[g * 4], bWh + offB + ko + g * 16 * LDK_ * 2);
                ldsm_x4(&bl[g * 4], bWl + offB + ko + g * 16 * LDK_ * 2);
            }
#pragma unroll
            for (int mt = 0; mt < 4; mt++)
#pragma unroll
                for (int nt = 0; nt < 4; nt++) {
                    mma16816h(acc[mt][nt], ah[mt], bh[nt * 2], bh[nt * 2 + 1]);
                    mma16816h(acc[mt][nt], ah[mt], bl[nt * 2], bl[nt * 2 + 1]);
                }
        }
    }
    __syncthreads();
}

// ===========================================================================
// fp16 1-combo GEMM mainloop (v, o projections), 3-stage ring.
// ===========================================================================
#define GEMM1_SMEM (6 * GARR)       // 3 stages x {A, W} = 60KB

__device__ __forceinline__ void gemm1_body(
    const __half* __restrict__ A, const __half* __restrict__ W,
    int m0, int n0, char* smem, float acc[4][4][4])
{
    const int tid    = threadIdx.x;
    const int lane   = tid & 31;
    const int wid    = tid >> 5;
    const int warp_m = wid & 1;
    const int warp_n = wid >> 1;
    const uint32_t sb = smem_u32(smem);

#pragma unroll
    for (int i = 0; i < 4; i++)
#pragma unroll
        for (int j = 0; j < 4; j++)
#pragma unroll
            for (int e = 0; e < 4; e++) acc[i][j][e] = 0.f;

    const int grow = tid >> 1;
    const int c16  = (tid & 1) * 2;
    const __half* s0 = A + (size_t)(m0 + grow) * D_;
    const __half* s1 = W + (size_t)(n0 + grow) * D_;

    auto issue = [&](int kc, int bsel) {
        const uint32_t dst = sb + bsel * 2 * GARR + grow * 80 + c16 * 16;
#pragma unroll
        for (int j = 0; j < 2; j++) {
            cp16(dst + j * 16,        s0 + kc + (c16 + j) * 8);
            cp16(dst + j * 16 + GARR, s1 + kc + (c16 + j) * 8);
        }
    };

    const int r_a = lane & 15, c_a = (lane >> 4) * 8;
    const int r_b = (lane & 7) | ((lane >> 4) << 3);
    const int c_b = ((lane >> 3) & 1) * 8;
    const uint32_t offA = ((warp_m * 64 + r_a) * LDK_ + c_a) * 2;
    const uint32_t offB = ((warp_n * 32 + r_b) * LDK_ + c_b) * 2;

    issue(0, 0);  CP_COMMIT();
    issue(32, 1); CP_COMMIT();

    const int NK = D_ / 32;   // 24
    for (int it = 0; it < NK; it++) {
        if (it + 1 < NK) { CP_WAIT(1); } else { CP_WAIT(0); }
        __syncthreads();
        if (it + 2 < NK) { issue((it + 2) * 32, (it + 2) % 3); CP_COMMIT(); }

        const uint32_t bA = sb + ((it % 3) * 2) * GARR;
        const uint32_t bW = bA + GARR;

#pragma unroll
        for (int ks = 0; ks < 2; ks++) {
            const uint32_t ko = ks * 32;
            uint32_t ah[4][4];
#pragma unroll
            for (int mt = 0; mt < 4; mt++)
                ldsm_x4(ah[mt], bA + offA + ko + mt * 16 * LDK_ * 2);
            uint32_t bh[8];
#pragma unroll
            for (int g = 0; g < 2; g++)
                ldsm_x4(&bh[g * 4], bW + offB + ko + g * 16 * LDK_ * 2);
#pragma unroll
            for (int mt = 0; mt < 4; mt++)
#pragma unroll
                for (int nt = 0; nt < 4; nt++)
                    mma16816h(acc[mt][nt], ah[mt], bh[nt * 2], bh[nt * 2 + 1]);
        }
    }
    __syncthreads();
}

// ===========================================================================
// fused QK GEMM (fp16 2-combo): proj + bias + L2 norm + scale(q) -> fp16.
// grid.x = 12 (wsel = x/6: 0=q, 1=k).
// ===========================================================================
__global__ void __launch_bounds__(256, 2)
qk_gemm(const float* __restrict__ bq, const float* __restrict__ bk,
        const float* __restrict__ ls)
{
    extern __shared__ char smem[];
    const int wsel = blockIdx.x / 6;
    const int n0   = (blockIdx.x % 6) * 128;
    const int m0   = blockIdx.y * 128;

    float acc[4][4][4];
    gemm2_body(g_xf, g_wh + (size_t)wsel * DD_, g_wl + (size_t)wsel * DD_,
               m0, n0, smem, acc);

    const int tid  = threadIdx.x;
    const int lane = tid & 31;
    const int wid  = tid >> 5;
    const int warp_m = wid & 1, warp_n = wid >> 1;

    const float* bias = (wsel == 0) ? bq : bk;
    __half* dst = (wsel == 0) ? g_qh : g_kh;

    float2 bv2[4];
#pragma unroll
    for (int nt = 0; nt < 4; nt++)
        bv2[nt] = *reinterpret_cast<const float2*>(
            &bias[n0 + warp_n * 32 + nt * 8 + 2 * (lane & 3)]);
#pragma unroll
    for (int mt = 0; mt < 4; mt++)
#pragma unroll
        for (int nt = 0; nt < 4; nt++) {
            acc[mt][nt][0] += bv2[nt].x; acc[mt][nt][1] += bv2[nt].y;
            acc[mt][nt][2] += bv2[nt].x; acc[mt][nt][3] += bv2[nt].y;
        }

    float* sq = reinterpret_cast<float*>(smem);   // [128][4]

#pragma unroll
    for (int mt = 0; mt < 4; mt++)
#pragma unroll
        for (int half = 0; half < 2; half++) {
            const int r = warp_m * 64 + mt * 16 + (lane >> 2) + half * 8;
            float p = 0.f;
#pragma unroll
            for (int nt = 0; nt < 4; nt++) {
                const float a = acc[mt][nt][half * 2], bvv = acc[mt][nt][half * 2 + 1];
                p += a * a + bvv * bvv;
            }
            p += __shfl_xor_sync(0xffffffffu, p, 1);
            p += __shfl_xor_sync(0xffffffffu, p, 2);
            if ((lane & 3) == 0) sq[r * 4 + warp_n] = p;
        }
    __syncthreads();

    float scl = 1.f;
    if (wsel == 0) {
        const int hh = 2 * (blockIdx.x % 6) + (warp_n >> 1);
        scl = __expf(fminf(ls[hh], 4.6051701859880914f)) * LOG2E_;
    }

#pragma unroll
    for (int mt = 0; mt < 4; mt++) {
#pragma unroll
        for (int half = 0; half < 2; half++) {
            const int r = warp_m * 64 + mt * 16 + (lane >> 2) + half * 8;
            const float s2 = sq[r * 4 + (warp_n & 2)] + sq[r * 4 + (warp_n & 2) + 1];
            const float inv = scl / fmaxf(sqrtf(s2), 1e-12f);
            const int m  = m0 + r;
            const int bb = m >> 11, ss = m & (S_ - 1);
#pragma unroll
            for (int nt = 0; nt < 4; nt++) {
                const int n  = n0 + warp_n * 32 + nt * 8 + 2 * (lane & 3);
                const int hh = n >> 6, dd = n & 63;
                const size_t idx = (((size_t)(bb * H_ + hh)) * S_ + ss) * DH_ + dd;
                *reinterpret_cast<uint32_t*>(&dst[idx]) =
                    pack2h(acc[mt][nt][half * 2] * inv, acc[mt][nt][half * 2 + 1] * inv);
            }
        }
    }
}

// v projection: x_f @ Wv^T + bv -> head-split fp16 g_vh
__global__ void __launch_bounds__(256, 2)
v_gemm(const float* __restrict__ bv)
{
    extern __shared__ char smem[];
    const int n0 = blockIdx.x * 128;
    const int m0 = blockIdx.y * 128;

    float acc[4][4][4];
    gemm1_body(g_xf, g_wvf, m0, n0, smem, acc);

    const int lane = threadIdx.x & 31;
    const int wid  = threadIdx.x >> 5;
    const int warp_m = wid & 1, warp_n = wid >> 1;
#pragma unroll
    for (int mt = 0; mt < 4; mt++) {
#pragma unroll
        for (int nt = 0; nt < 4; nt++) {
            const int n = n0 + warp_n * 32 + nt * 8 + 2 * (lane & 3);
            const float2 bv2 = *reinterpret_cast<const float2*>(&bv[n]);
            const int hh = n >> 6, dd = n & 63;
#pragma unroll
            for (int half = 0; half < 2; half++) {
                const int m = m0 + warp_m * 64 + mt * 16 + (lane >> 2) + half * 8;
                const int bb = m >> 11, ss = m & (S_ - 1);
                const size_t idx = (((size_t)(bb * H_ + hh)) * S_ + ss) * DH_ + dd;
                *reinterpret_cast<uint32_t*>(&g_vh[idx]) =
                    pack2h(acc[mt][nt][half * 2] + bv2.x,
                           acc[mt][nt][half * 2 + 1] + bv2.y);
            }
        }
    }
}

// output projection: ctx_f @ Wo^T + bo -> fp32 out
__global__ void __launch_bounds__(256, 2)
o_gemm(const float* __restrict__ bo, float* __restrict__ out)
{
    extern __shared__ char smem[];
    const int n0 = blockIdx.x * 128;
    const int m0 = blockIdx.y * 128;

    float acc[4][4][4];
    gemm1_body(g_cf, g_wof, m0, n0, smem, acc);

    const int lane = threadIdx.x & 31;
    const int wid  = threadIdx.x >> 5;
    const int warp_m = wid & 1, warp_n = wid >> 1;
#pragma unroll
    for (int mt = 0; mt < 4; mt++) {
#pragma unroll
        for (int nt = 0; nt < 4; nt++) {
            const int n = n0 + warp_n * 32 + nt * 8 + 2 * (lane & 3);
            const float2 bv2 = *reinterpret_cast<const float2*>(&bo[n]);
#pragma unroll
            for (int half = 0; half < 2; half++) {
                const int m = m0 + warp_m * 64 + mt * 16 + (lane >> 2) + half * 8;
                float2 o;
                o.x = acc[mt][nt][half * 2 + 0] + bv2.x;
                o.y = acc[mt][nt][half * 2 + 1] + bv2.y;
                *reinterpret_cast<float2*>(out + (size_t)m * D_ + n) = o;
            }
        }
    }
}

// ===========================================================================
// HMMA flash attention, fixed-max softmax, all single-fp16 tensor path.
// ===========================================================================
#define ABUF   9216
#define ATTN_SMEM (6 * ABUF)       // 3 stages x {Kh, Vh}

__global__ void __launch_bounds__(256, 2)
attn_mma(const float* __restrict__ ls)
{
    extern __shared__ char sm[];
    const uint32_t sbase = smem_u32(sm);
    const int tid  = threadIdx.x;
    const int lane = tid & 31;
    const int wid  = tid >> 5;
    const int bh   = blockIdx.y;
    const int h    = bh % H_;
    const int b    = bh / H_;
    const int q0   = blockIdx.x * 128;
    const size_t base = (size_t)bh * S_ * DH_;
    const float Mfix = __expf(fminf(ls[h], 4.6051701859880914f)) * LOG2E_;

    // stage Q (fp16, 128x64) into smem, build A-fragments, release
    {
        const __half* gq = g_qh + base + (size_t)q0 * DH_;
#pragma unroll
        for (int i = 0; i < 4; i++) {
            const int idx = (i << 8) + tid;
            const int row = idx >> 3, c = idx & 7;
            const uint4 v = *reinterpret_cast<const uint4*>(gq + row * DH_ + c * 8);
            *reinterpret_cast<uint4*>(sm + row * 144 + c * 16) = v;
        }
    }
    __syncthreads();
    uint32_t qf[4][4];
    {
        const uint32_t qa = sbase + (wid * 16 + (lane & 15)) * 144 + (lane >> 4) * 16;
#pragma unroll
        for (int kt = 0; kt < 4; kt++)
            ldsm_x4(qf[kt], qa + kt * 32);
    }
    __syncthreads();

    float o[8][4];
#pragma unroll
    for (int nt = 0; nt < 8; nt++)
#pragma unroll
        for (int e = 0; e < 4; e++) o[nt][e] = 0.f;
    float l0 = 0.f, l1 = 0.f;

    const uint32_t lofs = (lane & 15) * 144 + (lane >> 4) * 16;

    const __half* gkh = g_kh + base;
    const __half* gvh = g_vh + base;

    auto issue = [&](int it, int bsel) {
        const int koff = it * 64 * DH_;
#pragma unroll
        for (int i = 0; i < 4; i++) {
            const int idx = (i << 8) + tid;
            const int arr = idx >> 9;
            const int row = (idx >> 3) & 63;
            const int c   = idx & 7;
            const __half* gp = (arr == 0 ? gkh : gvh) + koff + row * DH_ + c * 8;
            cp16(sbase + (bsel * 2 + arr) * ABUF + row * 144 + c * 16, gp);
        }
    };

    issue(0, 0); CP_COMMIT();
    issue(1, 1); CP_COMMIT();

    const int NIT = S_ / 64;   // 32
    for (int it = 0; it < NIT; it++) {
        if (it + 1 < NIT) { CP_WAIT(1); } else { CP_WAIT(0); }
        __syncthreads();
        if (it + 2 < NIT) { issue(it + 2, (it + 2) % 3); CP_COMMIT(); }

        const uint32_t Kh = sbase + ((it % 3) * 2) * ABUF;
        const uint32_t Vh = Kh + ABUF;

        auto qk_block = [&](int g, float* s0p, float* s1p) {
#pragma unroll
            for (int e = 0; e < 4; e++) { s0p[e] = -Mfix; s1p[e] = -Mfix; }
#pragma unroll
            for (int kt = 0; kt < 4; kt++) {
                uint32_t kf[4];
                ldsm_x4(kf, Kh + lofs + g * 16 * 144 + kt * 32);
                mma16816h(s0p, qf[kt], kf[0], kf[2]);
                mma16816h(s1p, qf[kt], kf[1], kf[3]);
            }
        };
        auto exppack = [&](float* s0p, float* s1p, uint32_t* ph) {
#pragma unroll
            for (int e = 0; e < 4; e++) { s0p[e] = ex2(s0p[e]); s1p[e] = ex2(s1p[e]); }
            l0 += s0p[0] + s0p[1] + s1p[0] + s1p[1];
            l1 += s0p[2] + s0p[3] + s1p[2] + s1p[3];
            ph[0] = pack2h(s0p[0], s0p[1]);
            ph[1] = pack2h(s0p[2], s0p[3]);
            ph[2] = pack2h(s1p[0], s1p[1]);
            ph[3] = pack2h(s1p[2], s1p[3]);
        };
        auto pv_block = [&](int g, const uint32_t* ph) {
#pragma unroll
            for (int og = 0; og < 4; og++) {
                uint32_t vf[4];
                ldsm_x4_t(vf, Vh + lofs + g * 16 * 144 + og * 32);
                mma16816h(o[2 * og],     ph, vf[0], vf[1]);
                mma16816h(o[2 * og + 1], ph, vf[2], vf[3]);
            }
        };

        float sA0[4], sA1[4], sB0[4], sB1[4];
        uint32_t pA[4], pB[4];

        qk_block(0, sA0, sA1);
        exppack(sA0, sA1, pA);

        qk_block(1, sB0, sB1);
        pv_block(0, pA);
        exppack(sB0, sB1, pB);

        qk_block(2, sA0, sA1);
        pv_block(1, pB);
        exppack(sA0, sA1, pA);

        qk_block(3, sB0, sB1);
        pv_block(2, pA);
        exppack(sB0, sB1, pB);

        pv_block(3, pB);
    }

    // epilogue: quad-reduce l, normalize, store ctx as single fp16
    l0 += __shfl_xor_sync(0xffffffffu, l0, 1);
    l0 += __shfl_xor_sync(0xffffffffu, l0, 2);
    l1 += __shfl_xor_sync(0xffffffffu, l1, 1);
    l1 += __shfl_xor_sync(0xffffffffu, l1, 2);
    const float inv0 = 1.f / l0;
    const float inv1 = 1.f / l1;
    const int row0 = q0 + wid * 16 + (lane >> 2);
    const int col0 = h * DH_ + 2 * (lane & 3);
    const size_t p0 = ((size_t)b * S_ + row0) * D_ + col0;
    const size_t p1 = p0 + 8 * D_;
#pragma unroll
    for (int nt = 0; nt < 8; nt++) {
        *reinterpret_cast<uint32_t*>(g_cf + p0 + nt * 8) =
            pack2h(o[nt][0] * inv0, o[nt][1] * inv0);
        *reinterpret_cast<uint32_t*>(g_cf + p1 + nt * 8) =
            pack2h(o[nt][2] * inv1, o[nt][3] * inv1);
    }
}

// ---------------------------------------------------------------------------
// Launch
// ---------------------------------------------------------------------------
extern "C" void kernel_launch(void* const* d_in, const int* in_sizes, int n_in,
                              void* d_out, int out_size)
{
    const float* x  = (const float*)d_in[0];
    const float* Wq = (const float*)d_in[1];
    const float* bq = (const float*)d_in[2];
    const float* Wk = (const float*)d_in[3];
    const float* bk = (const float*)d_in[4];
    const float* Wv = (const float*)d_in[5];
    const float* bv = (const float*)d_in[6];
    const float* Wo = (const float*)d_in[7];
    const float* bo = (const float*)d_in[8];
    const float* ls = (const float*)d_in[9];
    float* out = (float*)d_out;

    xconv_kernel<<<(M_ * D_) / 1024, 256>>>(x);
    wsplit_kernel<<<4 * (DD_ / 1024), 256>>>(Wq, Wk, Wv, Wo);

    cudaFuncSetAttribute(qk_gemm, cudaFuncAttributeMaxDynamicSharedMemorySize, GEMM2_SMEM);
    cudaFuncSetAttribute(v_gemm,  cudaFuncAttributeMaxDynamicSharedMemorySize, GEMM1_SMEM);
    cudaFuncSetAttribute(o_gemm,  cudaFuncAttributeMaxDynamicSharedMemorySize, GEMM1_SMEM);
    cudaFuncSetAttribute(attn_mma, cudaFuncAttributeMaxDynamicSharedMemorySize, ATTN_SMEM);

    qk_gemm<<<dim3(12, M_ / 128), 256, GEMM2_SMEM>>>(bq, bk, ls);
    v_gemm<<<dim3(6, M_ / 128), 256, GEMM1_SMEM>>>(bv);

    attn_mma<<<dim3(S_ / 128, B_ * H_), 256, ATTN_SMEM>>>(ls);

    o_gemm<<<dim3(6, M_ / 128), 256, GEMM1_SMEM>>>(bo, out);
}